// round 1
// baseline (speedup 1.0000x reference)
#include <cuda_runtime.h>
#include <cstdint>

#define WS        7
#define NTOK      49        // 7*7
#define CCH       128
#define NH        4
#define DH        32
#define HWDIM     56
#define SHIFT     3

// shared memory layout (floats)
#define XS_OFF    0                     // xs  [49][128]           6272 floats
#define QKV_STR   385                   // padded row stride (odd mod 32 -> conflict-free column reads)
#define QKV_OFF   6272                  // qkv [49][385]          18865 floats (pad to 18868)
#define SCR_OFF   25140                 // union: wt[128][64] (8192 f) OR attn[4][49*50] (9800 f)
#define ATT_STR   50
#define SMEM_FLOATS (SCR_OFF + 9800)    // 34940 floats
#define SMEM_BYTES  (SMEM_FLOATS * 4)   // 139760 B

__global__ __launch_bounds__(256, 1)
void swin_block_kernel(const float* __restrict__ x,
                       const float* __restrict__ w_qkv,
                       const float* __restrict__ b_qkv,
                       const float* __restrict__ w_proj,
                       const float* __restrict__ b_proj,
                       const float* __restrict__ rel_table,
                       float* __restrict__ out)
{
    extern __shared__ float smem[];
    float* xs  = smem + XS_OFF;     // [49][128] : input window, later attention output O
    float* qkv = smem + QKV_OFF;    // [49][385] : q(0..127) k(128..255) v(256..383)
    float* scr = smem + SCR_OFF;    // weight tile [128][64]  /  attn [4][49*50]
    __shared__ int lab[NTOK];       // shift-mask region labels

    const int tid  = threadIdx.x;
    const int b    = blockIdx.x >> 6;
    const int widx = blockIdx.x & 63;
    const int wy   = widx >> 3;
    const int wx   = widx & 7;

    // ---------------- Phase 1: load rolled window + labels ----------------
    for (int t = tid; t < NTOK * 32; t += 256) {
        int n  = t >> 5, c4 = t & 31;
        int i  = n / 7, j = n - i * 7;
        int r  = wy * 7 + i + SHIFT; if (r  >= HWDIM) r  -= HWDIM;
        int cc = wx * 7 + j + SHIFT; if (cc >= HWDIM) cc -= HWDIM;
        const float4 v = reinterpret_cast<const float4*>(
            x + ((size_t)(b * HWDIM + r) * HWDIM + cc) * CCH)[c4];
        reinterpret_cast<float4*>(xs + n * CCH)[c4] = v;
    }
    if (tid < NTOK) {
        int i = tid / 7, j = tid - (tid / 7) * 7;
        int sh = wy * 7 + i, sw = wx * 7 + j;
        int rh = (sh < 49) ? 0 : ((sh < 53) ? 1 : 2);
        int rw = (sw < 49) ? 0 : ((sw < 53) ? 1 : 2);
        lab[tid] = rh * 3 + rw;
    }
    __syncthreads();

    // ---------------- Phase 2: QKV GEMM (49x128 @ 128x384) ----------------
    const int ty = tid >> 4;   // 0..15 -> rows ty, ty+16, ty+32, (48)
    const int tx = tid & 15;   // 0..15 -> cols tx*4 .. tx*4+3 within a 64-col tile

    for (int tile = 0; tile < 6; ++tile) {
        for (int t = tid; t < 128 * 16; t += 256) {
            int k = t >> 4, c4 = t & 15;
            reinterpret_cast<float4*>(scr + k * 64)[c4] =
                reinterpret_cast<const float4*>(w_qkv + k * 384 + tile * 64)[c4];
        }
        __syncthreads();

        float acc[4][4];
        #pragma unroll
        for (int a = 0; a < 4; ++a)
            #pragma unroll
            for (int c = 0; c < 4; ++c) acc[a][c] = 0.f;

        const float* xr0 = xs + ty * CCH;
        const float* xr1 = xs + (ty + 16) * CCH;
        const float* xr2 = xs + (ty + 32) * CCH;
        const float* xr3 = xs + 48 * CCH;

        #pragma unroll 4
        for (int k = 0; k < 128; ++k) {
            float4 w4 = reinterpret_cast<const float4*>(scr + k * 64 + tx * 4)[0];
            float x0 = xr0[k], x1 = xr1[k], x2 = xr2[k], x3 = xr3[k];
            acc[0][0] += x0 * w4.x; acc[0][1] += x0 * w4.y; acc[0][2] += x0 * w4.z; acc[0][3] += x0 * w4.w;
            acc[1][0] += x1 * w4.x; acc[1][1] += x1 * w4.y; acc[1][2] += x1 * w4.z; acc[1][3] += x1 * w4.w;
            acc[2][0] += x2 * w4.x; acc[2][1] += x2 * w4.y; acc[2][2] += x2 * w4.z; acc[2][3] += x2 * w4.w;
            acc[3][0] += x3 * w4.x; acc[3][1] += x3 * w4.y; acc[3][2] += x3 * w4.z; acc[3][3] += x3 * w4.w;
        }

        const int cbase = tile * 64 + tx * 4;
        const float4 bb = reinterpret_cast<const float4*>(b_qkv + cbase)[0];
        float* q0 = qkv + ty * QKV_STR + cbase;
        q0[0] = acc[0][0] + bb.x; q0[1] = acc[0][1] + bb.y; q0[2] = acc[0][2] + bb.z; q0[3] = acc[0][3] + bb.w;
        float* q1 = qkv + (ty + 16) * QKV_STR + cbase;
        q1[0] = acc[1][0] + bb.x; q1[1] = acc[1][1] + bb.y; q1[2] = acc[1][2] + bb.z; q1[3] = acc[1][3] + bb.w;
        float* q2 = qkv + (ty + 32) * QKV_STR + cbase;
        q2[0] = acc[2][0] + bb.x; q2[1] = acc[2][1] + bb.y; q2[2] = acc[2][2] + bb.z; q2[3] = acc[2][3] + bb.w;
        if (ty == 0) {
            float* q3 = qkv + 48 * QKV_STR + cbase;
            q3[0] = acc[3][0] + bb.x; q3[1] = acc[3][1] + bb.y; q3[2] = acc[3][2] + bb.z; q3[3] = acc[3][3] + bb.w;
        }
        __syncthreads();
    }

    // ---------------- Phase 3: attention (64 threads per head) ----------------
    const int head = tid >> 6;          // 0..3
    const int lt   = tid & 63;          // 0..63 within head
    const float* qh = qkv + head * DH;
    const float* kh = qkv + 128 + head * DH;
    const float* vh = qkv + 256 + head * DH;
    float* ah = scr + head * (NTOK * ATT_STR);
    const float scale = 0.17677669529663687f;  // 32^-0.5

    // S = scale * q @ k^T
    for (int idx = lt; idx < NTOK * NTOK; idx += 64) {
        int i = idx / 49, j = idx - i * 49;
        const float* qr = qh + i * QKV_STR;
        const float* kr = kh + j * QKV_STR;
        float s = 0.f;
        #pragma unroll
        for (int k = 0; k < DH; ++k) s += qr[k] * kr[k];
        ah[i * ATT_STR + j] = s * scale;
    }
    __syncthreads();

    // softmax per row, THEN add rel-pos bias and shift mask (faithful to source)
    if (lt < NTOK) {
        const int i = lt;
        float* row = ah + i * ATT_STR;
        float m = row[0];
        for (int j = 1; j < NTOK; ++j) m = fmaxf(m, row[j]);
        float sum = 0.f;
        for (int j = 0; j < NTOK; ++j) { float e = __expf(row[j] - m); row[j] = e; sum += e; }
        const float inv = 1.f / sum;
        const int yi = i / 7, xi = i - yi * 7;
        const int li = lab[i];
        for (int j = 0; j < NTOK; ++j) {
            int yj = j / 7, xj = j - yj * 7;
            int bidx = ((yi - yj + 6) * 13 + (xi - xj + 6)) * NH + head;
            float bias = rel_table[bidx];
            float mk = (lab[j] != li) ? -100.f : 0.f;
            row[j] = row[j] * inv + bias + mk;
        }
    }
    __syncthreads();

    // O = attn @ V  -> reuse xs as O[49][128]
    for (int idx = lt; idx < NTOK * DH; idx += 64) {
        int i = idx >> 5, dd = idx & 31;
        const float* ar = ah + i * ATT_STR;
        const float* vp = vh + dd;
        float s = 0.f;
        #pragma unroll 7
        for (int j = 0; j < NTOK; ++j) s += ar[j] * vp[j * QKV_STR];
        xs[i * CCH + head * DH + dd] = s;
    }
    __syncthreads();

    // ---------------- Phase 4: proj GEMM + window-reverse + roll-back write ----------------
    for (int tile = 0; tile < 2; ++tile) {
        for (int t = tid; t < 128 * 16; t += 256) {
            int k = t >> 4, c4 = t & 15;
            reinterpret_cast<float4*>(scr + k * 64)[c4] =
                reinterpret_cast<const float4*>(w_proj + k * 128 + tile * 64)[c4];
        }
        __syncthreads();

        float acc[4][4];
        #pragma unroll
        for (int a = 0; a < 4; ++a)
            #pragma unroll
            for (int c = 0; c < 4; ++c) acc[a][c] = 0.f;

        const float* xr0 = xs + ty * CCH;
        const float* xr1 = xs + (ty + 16) * CCH;
        const float* xr2 = xs + (ty + 32) * CCH;
        const float* xr3 = xs + 48 * CCH;

        #pragma unroll 4
        for (int k = 0; k < 128; ++k) {
            float4 w4 = reinterpret_cast<const float4*>(scr + k * 64 + tx * 4)[0];
            float x0 = xr0[k], x1 = xr1[k], x2 = xr2[k], x3 = xr3[k];
            acc[0][0] += x0 * w4.x; acc[0][1] += x0 * w4.y; acc[0][2] += x0 * w4.z; acc[0][3] += x0 * w4.w;
            acc[1][0] += x1 * w4.x; acc[1][1] += x1 * w4.y; acc[1][2] += x1 * w4.z; acc[1][3] += x1 * w4.w;
            acc[2][0] += x2 * w4.x; acc[2][1] += x2 * w4.y; acc[2][2] += x2 * w4.z; acc[2][3] += x2 * w4.w;
            acc[3][0] += x3 * w4.x; acc[3][1] += x3 * w4.y; acc[3][2] += x3 * w4.z; acc[3][3] += x3 * w4.w;
        }

        const int cbase = tile * 64 + tx * 4;
        const float4 bb = reinterpret_cast<const float4*>(b_proj + cbase)[0];

        #pragma unroll
        for (int rr = 0; rr < 4; ++rr) {
            int n = (rr < 3) ? (ty + 16 * rr) : 48;
            if (rr == 3 && ty != 0) break;
            int i = n / 7, j = n - (n / 7) * 7;
            int r  = wy * 7 + i + SHIFT; if (r  >= HWDIM) r  -= HWDIM;
            int cc = wx * 7 + j + SHIFT; if (cc >= HWDIM) cc -= HWDIM;
            float4 v;
            v.x = acc[rr][0] + bb.x; v.y = acc[rr][1] + bb.y;
            v.z = acc[rr][2] + bb.z; v.w = acc[rr][3] + bb.w;
            reinterpret_cast<float4*>(
                out + ((size_t)(b * HWDIM + r) * HWDIM + cc) * CCH + cbase)[0] = v;
        }
        __syncthreads();
    }
}

extern "C" void kernel_launch(void* const* d_in, const int* in_sizes, int n_in,
                              void* d_out, int out_size)
{
    const float* x         = (const float*)d_in[0];
    const float* w_qkv     = (const float*)d_in[1];
    const float* b_qkv     = (const float*)d_in[2];
    const float* w_proj    = (const float*)d_in[3];
    const float* b_proj    = (const float*)d_in[4];
    const float* rel_table = (const float*)d_in[5];
    float* out = (float*)d_out;

    cudaFuncSetAttribute(swin_block_kernel,
                         cudaFuncAttributeMaxDynamicSharedMemorySize, SMEM_BYTES);

    dim3 grid(64 * 64);   // 64 batches * 64 windows
    dim3 block(256);
    swin_block_kernel<<<grid, block, SMEM_BYTES>>>(
        x, w_qkv, b_qkv, w_proj, b_proj, rel_table, out);
}

// round 3
// speedup vs baseline: 1.1990x; 1.1990x over previous
#include <cuda_runtime.h>
#include <cstdint>

#define WS        7
#define NTOK      49        // 7*7
#define CCH       128
#define NH        4
#define DH        32
#define HWDIM     56
#define SHIFT     3

// shared memory layout (floats)
#define XS_OFF    0                     // xs  [49][128]        6272 floats (input window, later O)
#define QKV_STR   385                   // odd stride -> conflict-free K/V column reads
#define QKV_OFF   6272                  // qkv [49][385]        18865 -> pad 18868
#define SCR_OFF   25140                 // union: wtile [128][128] (16384 f)  OR attn [4][49*50] (9800 f)
#define ATT_STR   50
#define SMEM_FLOATS (SCR_OFF + 16384)   // 41524 floats
#define SMEM_BYTES  (SMEM_FLOATS * 4)   // 166096 B

__global__ __launch_bounds__(256, 1)
void swin_block_kernel(const float* __restrict__ x,
                       const float* __restrict__ w_qkv,
                       const float* __restrict__ b_qkv,
                       const float* __restrict__ w_proj,
                       const float* __restrict__ b_proj,
                       const float* __restrict__ rel_table,
                       float* __restrict__ out)
{
    extern __shared__ float smem[];
    float* xs  = smem + XS_OFF;
    float* qkv = smem + QKV_OFF;
    float* scr = smem + SCR_OFF;
    __shared__ int lab[NTOK];

    const int tid  = threadIdx.x;
    const int warp = tid >> 5;
    const int lane = tid & 31;
    const int b    = blockIdx.x >> 6;
    const int widx = blockIdx.x & 63;
    const int wy   = widx >> 3;
    const int wx   = widx & 7;

    // ---------------- Phase 1: load rolled window + labels ----------------
    for (int t = tid; t < NTOK * 32; t += 256) {
        int n  = t >> 5, c4 = t & 31;
        int i  = n / 7, j = n - i * 7;
        int r  = wy * 7 + i + SHIFT; if (r  >= HWDIM) r  -= HWDIM;
        int cc = wx * 7 + j + SHIFT; if (cc >= HWDIM) cc -= HWDIM;
        const float4 v = reinterpret_cast<const float4*>(
            x + ((size_t)(b * HWDIM + r) * HWDIM + cc) * CCH)[c4];
        reinterpret_cast<float4*>(xs + n * CCH)[c4] = v;
    }
    if (tid < NTOK) {
        int i = tid / 7, j = tid - (tid / 7) * 7;
        int sh = wy * 7 + i, sw = wx * 7 + j;
        int rh = (sh < 49) ? 0 : ((sh < 53) ? 1 : 2);
        int rw = (sw < 49) ? 0 : ((sw < 53) ? 1 : 2);
        lab[tid] = rh * 3 + rw;
    }
    __syncthreads();

    // ---------------- Phase 2: QKV GEMM (49x128 @ 128x384) ----------------
    // warps 0..6 each own 7 contiguous rows; each lane owns 4 cols of a
    // 128-col staged weight tile. x rows read as broadcast float4.
    for (int g = 0; g < 3; ++g) {
        // stage w_qkv[:, g*128 : g*128+128] -> scr [128][128]
        for (int t = tid; t < 128 * 32; t += 256) {
            int r = t >> 5, c = t & 31;
            reinterpret_cast<float4*>(scr + r * 128)[c] =
                reinterpret_cast<const float4*>(w_qkv + r * 384 + g * 128)[c];
        }
        __syncthreads();

        if (warp < 7) {
            float acc[7][4];
            #pragma unroll
            for (int r = 0; r < 7; ++r)
                #pragma unroll
                for (int c = 0; c < 4; ++c) acc[r][c] = 0.f;

            const float* xbase = xs + warp * 7 * CCH;
            const float* wcol  = scr + lane * 4;

            for (int k4 = 0; k4 < 32; ++k4) {
                float4 xv[7];
                #pragma unroll
                for (int r = 0; r < 7; ++r)
                    xv[r] = reinterpret_cast<const float4*>(xbase + r * CCH)[k4];
                #pragma unroll
                for (int kk = 0; kk < 4; ++kk) {
                    float4 w4 = reinterpret_cast<const float4*>(wcol + (k4 * 4 + kk) * 128)[0];
                    #pragma unroll
                    for (int r = 0; r < 7; ++r) {
                        float xvk = (kk == 0) ? xv[r].x : (kk == 1) ? xv[r].y
                                  : (kk == 2) ? xv[r].z : xv[r].w;
                        acc[r][0] += xvk * w4.x;
                        acc[r][1] += xvk * w4.y;
                        acc[r][2] += xvk * w4.z;
                        acc[r][3] += xvk * w4.w;
                    }
                }
            }

            const int cb = g * 128 + lane * 4;
            const float4 bb = reinterpret_cast<const float4*>(b_qkv + cb)[0];
            #pragma unroll
            for (int r = 0; r < 7; ++r) {
                float* dst = qkv + (warp * 7 + r) * QKV_STR + cb;
                dst[0] = acc[r][0] + bb.x;
                dst[1] = acc[r][1] + bb.y;
                dst[2] = acc[r][2] + bb.z;
                dst[3] = acc[r][3] + bb.w;
            }
        }
        __syncthreads();
    }

    // ---------------- Phase 3: attention (64 threads per head) ----------------
    const int head = tid >> 6;
    const int lt   = tid & 63;
    const float* qh = qkv + head * DH;
    const float* kh = qkv + 128 + head * DH;
    const float* vh = qkv + 256 + head * DH;
    float* ah = scr + head * (NTOK * ATT_STR);
    const float scale = 0.17677669529663687f;  // 32^-0.5

    // S = scale * q @ k^T
    for (int idx = lt; idx < NTOK * NTOK; idx += 64) {
        int i = idx / 49, j = idx - i * 49;
        const float* qr = qh + i * QKV_STR;
        const float* kr = kh + j * QKV_STR;
        float s = 0.f;
        #pragma unroll
        for (int k = 0; k < DH; ++k) s += qr[k] * kr[k];
        ah[i * ATT_STR + j] = s * scale;
    }
    __syncthreads();

    // softmax per row, THEN add rel-pos bias and shift mask (faithful to source)
    if (lt < NTOK) {
        const int i = lt;
        float* row = ah + i * ATT_STR;
        float m = row[0];
        for (int j = 1; j < NTOK; ++j) m = fmaxf(m, row[j]);
        float sum = 0.f;
        for (int j = 0; j < NTOK; ++j) { float e = __expf(row[j] - m); row[j] = e; sum += e; }
        const float inv = 1.f / sum;
        const int yi = i / 7, xi = i - yi * 7;
        const int li = lab[i];
        for (int j = 0; j < NTOK; ++j) {
            int yj = j / 7, xj = j - yj * 7;
            int bidx = ((yi - yj + 6) * 13 + (xi - xj + 6)) * NH + head;
            float bias = rel_table[bidx];
            float mk = (lab[j] != li) ? -100.f : 0.f;
            row[j] = row[j] * inv + bias + mk;
        }
    }
    __syncthreads();

    // O = attn @ V  -> reuse xs as O[49][128]
    for (int idx = lt; idx < NTOK * DH; idx += 64) {
        int i = idx >> 5, dd = idx & 31;
        const float* ar = ah + i * ATT_STR;
        const float* vp = vh + dd;
        float s = 0.f;
        #pragma unroll 7
        for (int j = 0; j < NTOK; ++j) s += ar[j] * vp[j * QKV_STR];
        xs[i * CCH + head * DH + dd] = s;
    }
    __syncthreads();

    // ---------------- Phase 4: proj GEMM + window-reverse + roll-back write ----------------
    // stage w_proj [128][128]
    for (int t = tid; t < 128 * 32; t += 256) {
        int r = t >> 5, c = t & 31;
        reinterpret_cast<float4*>(scr + r * 128)[c] =
            reinterpret_cast<const float4*>(w_proj + r * 128)[c];
    }
    __syncthreads();

    if (warp < 7) {
        float acc[7][4];
        #pragma unroll
        for (int r = 0; r < 7; ++r)
            #pragma unroll
            for (int c = 0; c < 4; ++c) acc[r][c] = 0.f;

        const float* xbase = xs + warp * 7 * CCH;
        const float* wcol  = scr + lane * 4;

        for (int k4 = 0; k4 < 32; ++k4) {
            float4 xv[7];
            #pragma unroll
            for (int r = 0; r < 7; ++r)
                xv[r] = reinterpret_cast<const float4*>(xbase + r * CCH)[k4];
            #pragma unroll
            for (int kk = 0; kk < 4; ++kk) {
                float4 w4 = reinterpret_cast<const float4*>(wcol + (k4 * 4 + kk) * 128)[0];
                #pragma unroll
                for (int r = 0; r < 7; ++r) {
                    float xvk = (kk == 0) ? xv[r].x : (kk == 1) ? xv[r].y
                              : (kk == 2) ? xv[r].z : xv[r].w;
                    acc[r][0] += xvk * w4.x;
                    acc[r][1] += xvk * w4.y;
                    acc[r][2] += xvk * w4.z;
                    acc[r][3] += xvk * w4.w;
                }
            }
        }

        const float4 bb = reinterpret_cast<const float4*>(b_proj + lane * 4)[0];

        // rows 7*warp + r  ->  i = warp, j = r  (window coords)
        int rg = wy * 7 + warp + SHIFT; if (rg >= HWDIM) rg -= HWDIM;
        #pragma unroll
        for (int r = 0; r < 7; ++r) {
            int cg = wx * 7 + r + SHIFT; if (cg >= HWDIM) cg -= HWDIM;
            float4 v;
            v.x = acc[r][0] + bb.x; v.y = acc[r][1] + bb.y;
            v.z = acc[r][2] + bb.z; v.w = acc[r][3] + bb.w;
            reinterpret_cast<float4*>(
                out + ((size_t)(b * HWDIM + rg) * HWDIM + cg) * CCH + lane * 4)[0] = v;
        }
    }
}

extern "C" void kernel_launch(void* const* d_in, const int* in_sizes, int n_in,
                              void* d_out, int out_size)
{
    const float* x         = (const float*)d_in[0];
    const float* w_qkv     = (const float*)d_in[1];
    const float* b_qkv     = (const float*)d_in[2];
    const float* w_proj    = (const float*)d_in[3];
    const float* b_proj    = (const float*)d_in[4];
    const float* rel_table = (const float*)d_in[5];
    float* out = (float*)d_out;

    cudaFuncSetAttribute(swin_block_kernel,
                         cudaFuncAttributeMaxDynamicSharedMemorySize, SMEM_BYTES);

    dim3 grid(64 * 64);   // 64 batches * 64 windows
    dim3 block(256);
    swin_block_kernel<<<grid, block, SMEM_BYTES>>>(
        x, w_qkv, b_qkv, w_proj, b_proj, rel_table, out);
}

// round 4
// speedup vs baseline: 1.4534x; 1.2122x over previous
#include <cuda_runtime.h>
#include <cstdint>

#define WS        7
#define NTOK      49
#define CCH       128
#define NH        4
#define DH        32
#define HWDIM     56
#define SHIFT     3

// shared memory layout (floats)
#define XS_STR    132                   // padded O/x row stride (33 x 16B, odd 16B-units)
#define XS_OFF    0                     // xs [49][132]  = 6468 floats
#define QKV_STR   388                   // mult of 4 (aligned float4), 97 16B-units (odd -> conflict-free)
#define QKV_OFF   6468                  // qkv [49][388] = 19012 floats
#define SCR_OFF   25480                 // union: wtile [128][128] (16384) OR attn [4][49*51] (9996)
#define ATT_STR   51
#define SMEM_FLOATS (SCR_OFF + 16384)   // 41864 floats
#define SMEM_BYTES  (SMEM_FLOATS * 4)   // 167456 B

__global__ __launch_bounds__(256, 1)
void swin_block_kernel(const float* __restrict__ x,
                       const float* __restrict__ w_qkv,
                       const float* __restrict__ b_qkv,
                       const float* __restrict__ w_proj,
                       const float* __restrict__ b_proj,
                       const float* __restrict__ rel_table,
                       float* __restrict__ out)
{
    extern __shared__ float smem[];
    float* xs  = smem + XS_OFF;
    float* qkv = smem + QKV_OFF;
    float* scr = smem + SCR_OFF;
    __shared__ int lab[NTOK];

    const int tid  = threadIdx.x;
    const int warp = tid >> 5;
    const int lane = tid & 31;
    const int b    = blockIdx.x >> 6;
    const int widx = blockIdx.x & 63;
    const int wy   = widx >> 3;
    const int wx   = widx & 7;

    // ---------------- Phase 1: load rolled window + labels ----------------
    for (int t = tid; t < NTOK * 32; t += 256) {
        int n  = t >> 5, c4 = t & 31;
        int i  = n / 7, j = n - i * 7;
        int r  = wy * 7 + i + SHIFT; if (r  >= HWDIM) r  -= HWDIM;
        int cc = wx * 7 + j + SHIFT; if (cc >= HWDIM) cc -= HWDIM;
        const float4 v = reinterpret_cast<const float4*>(
            x + ((size_t)(b * HWDIM + r) * HWDIM + cc) * CCH)[c4];
        reinterpret_cast<float4*>(xs + n * XS_STR)[c4] = v;
    }
    if (tid < NTOK) {
        int i = tid / 7, j = tid - (tid / 7) * 7;
        int sh = wy * 7 + i, sw = wx * 7 + j;
        int rh = (sh < 49) ? 0 : ((sh < 53) ? 1 : 2);
        int rw = (sw < 49) ? 0 : ((sw < 53) ? 1 : 2);
        lab[tid] = rh * 3 + rw;
    }
    __syncthreads();

    // ---------------- Phase 2: QKV GEMM (49x128 @ 128x384) ----------------
    for (int g = 0; g < 3; ++g) {
        for (int t = tid; t < 128 * 32; t += 256) {
            int r = t >> 5, c = t & 31;
            reinterpret_cast<float4*>(scr + r * 128)[c] =
                reinterpret_cast<const float4*>(w_qkv + r * 384 + g * 128)[c];
        }
        __syncthreads();

        if (warp < 7) {
            float acc[7][4];
            #pragma unroll
            for (int r = 0; r < 7; ++r)
                #pragma unroll
                for (int c = 0; c < 4; ++c) acc[r][c] = 0.f;

            const float* xbase = xs + warp * 7 * XS_STR;
            const float* wcol  = scr + lane * 4;

            for (int k4 = 0; k4 < 32; ++k4) {
                float4 xv[7];
                #pragma unroll
                for (int r = 0; r < 7; ++r)
                    xv[r] = reinterpret_cast<const float4*>(xbase + r * XS_STR)[k4];
                #pragma unroll
                for (int kk = 0; kk < 4; ++kk) {
                    float4 w4 = reinterpret_cast<const float4*>(wcol + (k4 * 4 + kk) * 128)[0];
                    #pragma unroll
                    for (int r = 0; r < 7; ++r) {
                        float xvk = (kk == 0) ? xv[r].x : (kk == 1) ? xv[r].y
                                  : (kk == 2) ? xv[r].z : xv[r].w;
                        acc[r][0] += xvk * w4.x;
                        acc[r][1] += xvk * w4.y;
                        acc[r][2] += xvk * w4.z;
                        acc[r][3] += xvk * w4.w;
                    }
                }
            }

            const int cb = g * 128 + lane * 4;
            const float4 bb = reinterpret_cast<const float4*>(b_qkv + cb)[0];
            #pragma unroll
            for (int r = 0; r < 7; ++r) {
                float* dst = qkv + (warp * 7 + r) * QKV_STR + cb;
                dst[0] = acc[r][0] + bb.x;
                dst[1] = acc[r][1] + bb.y;
                dst[2] = acc[r][2] + bb.z;
                dst[3] = acc[r][3] + bb.w;
            }
        }
        __syncthreads();
    }

    // ---------------- Phase 3: attention, row-per-thread ----------------
    const int head = tid >> 6;          // 0..3
    const int lt   = tid & 63;          // 0..63 ; active rows lt<49
    const int i    = lt;
    const bool act = (lt < NTOK);
    float* ah = scr + head * (NTOK * ATT_STR);
    const float scale = 0.17677669529663687f;  // 32^-0.5

    // q row -> registers
    float4 q4[8];
    {
        const float4* qr = reinterpret_cast<const float4*>(
            qkv + (act ? i : 0) * QKV_STR + head * DH);
        #pragma unroll
        for (int m = 0; m < 8; ++m) q4[m] = qr[m];
    }

    // S = scale * q @ k^T, fused row max
    float mx = -1e30f;
    const float* kbase = qkv + CCH + head * DH;
    #pragma unroll 1
    for (int j = 0; j < NTOK; ++j) {
        const float4* kr = reinterpret_cast<const float4*>(kbase + j * QKV_STR);
        float s = 0.f;
        #pragma unroll
        for (int m = 0; m < 8; ++m) {
            float4 k4 = kr[m];   // broadcast
            s += q4[m].x * k4.x + q4[m].y * k4.y + q4[m].z * k4.z + q4[m].w * k4.w;
        }
        s *= scale;
        if (act) { ah[i * ATT_STR + j] = s; mx = fmaxf(mx, s); }
    }
    __syncthreads();

    // softmax per row, THEN add rel-pos bias and shift mask (faithful to source)
    if (act) {
        float* row = ah + i * ATT_STR;
        float sum = 0.f;
        #pragma unroll 1
        for (int j = 0; j < NTOK; ++j) {
            float e = __expf(row[j] - mx); row[j] = e; sum += e;
        }
        const float inv = 1.f / sum;
        const int yi = i / 7, xi = i - yi * 7;
        const int li = lab[i];
        #pragma unroll 1
        for (int j = 0; j < NTOK; ++j) {
            int yj = j / 7, xj = j - yj * 7;
            int bidx = ((yi - yj + 6) * 13 + (xi - xj + 6)) * NH + head;
            float bias = __ldg(rel_table + bidx);
            float mk = (lab[j] != li) ? -100.f : 0.f;
            row[j] = row[j] * inv + bias + mk;
        }
    }
    __syncthreads();

    // O = attn @ V  (row-per-thread, V broadcast), write to xs
    {
        float acc[32];
        #pragma unroll
        for (int d = 0; d < 32; ++d) acc[d] = 0.f;
        const float* vbase = qkv + 2 * CCH + head * DH;
        #pragma unroll 1
        for (int j = 0; j < NTOK; ++j) {
            float a = act ? ah[i * ATT_STR + j] : 0.f;
            const float4* vr = reinterpret_cast<const float4*>(vbase + j * QKV_STR);
            #pragma unroll
            for (int m = 0; m < 8; ++m) {
                float4 v4 = vr[m];   // broadcast
                acc[4 * m + 0] += a * v4.x;
                acc[4 * m + 1] += a * v4.y;
                acc[4 * m + 2] += a * v4.z;
                acc[4 * m + 3] += a * v4.w;
            }
        }
        if (act) {
            float4* dst = reinterpret_cast<float4*>(xs + i * XS_STR + head * DH);
            #pragma unroll
            for (int m = 0; m < 8; ++m)
                dst[m] = make_float4(acc[4 * m], acc[4 * m + 1], acc[4 * m + 2], acc[4 * m + 3]);
        }
    }
    __syncthreads();

    // ---------------- Phase 4: proj GEMM + window-reverse + roll-back write ----------------
    for (int t = tid; t < 128 * 32; t += 256) {
        int r = t >> 5, c = t & 31;
        reinterpret_cast<float4*>(scr + r * 128)[c] =
            reinterpret_cast<const float4*>(w_proj + r * 128)[c];
    }
    __syncthreads();

    if (warp < 7) {
        float acc[7][4];
        #pragma unroll
        for (int r = 0; r < 7; ++r)
            #pragma unroll
            for (int c = 0; c < 4; ++c) acc[r][c] = 0.f;

        const float* xbase = xs + warp * 7 * XS_STR;
        const float* wcol  = scr + lane * 4;

        for (int k4 = 0; k4 < 32; ++k4) {
            float4 xv[7];
            #pragma unroll
            for (int r = 0; r < 7; ++r)
                xv[r] = reinterpret_cast<const float4*>(xbase + r * XS_STR)[k4];
            #pragma unroll
            for (int kk = 0; kk < 4; ++kk) {
                float4 w4 = reinterpret_cast<const float4*>(wcol + (k4 * 4 + kk) * 128)[0];
                #pragma unroll
                for (int r = 0; r < 7; ++r) {
                    float xvk = (kk == 0) ? xv[r].x : (kk == 1) ? xv[r].y
                              : (kk == 2) ? xv[r].z : xv[r].w;
                    acc[r][0] += xvk * w4.x;
                    acc[r][1] += xvk * w4.y;
                    acc[r][2] += xvk * w4.z;
                    acc[r][3] += xvk * w4.w;
                }
            }
        }

        const float4 bb = reinterpret_cast<const float4*>(b_proj + lane * 4)[0];

        int rg = wy * 7 + warp + SHIFT; if (rg >= HWDIM) rg -= HWDIM;
        #pragma unroll
        for (int r = 0; r < 7; ++r) {
            int cg = wx * 7 + r + SHIFT; if (cg >= HWDIM) cg -= HWDIM;
            float4 v;
            v.x = acc[r][0] + bb.x; v.y = acc[r][1] + bb.y;
            v.z = acc[r][2] + bb.z; v.w = acc[r][3] + bb.w;
            reinterpret_cast<float4*>(
                out + ((size_t)(b * HWDIM + rg) * HWDIM + cg) * CCH + lane * 4)[0] = v;
        }
    }
}

extern "C" void kernel_launch(void* const* d_in, const int* in_sizes, int n_in,
                              void* d_out, int out_size)
{
    const float* x         = (const float*)d_in[0];
    const float* w_qkv     = (const float*)d_in[1];
    const float* b_qkv     = (const float*)d_in[2];
    const float* w_proj    = (const float*)d_in[3];
    const float* b_proj    = (const float*)d_in[4];
    const float* rel_table = (const float*)d_in[5];
    float* out = (float*)d_out;

    cudaFuncSetAttribute(swin_block_kernel,
                         cudaFuncAttributeMaxDynamicSharedMemorySize, SMEM_BYTES);

    dim3 grid(64 * 64);
    dim3 block(256);
    swin_block_kernel<<<grid, block, SMEM_BYTES>>>(
        x, w_qkv, b_qkv, w_proj, b_proj, rel_table, out);
}

// round 6
// speedup vs baseline: 1.9398x; 1.3346x over previous
#include <cuda_runtime.h>
#include <cstdint>

#define NTOK      49
#define CCH       128
#define NH        4
#define DH        32
#define HWDIM     56
#define SHIFT     3
#define SCALE     0.17677669529663687f   // 32^-0.5

// dynamic shared memory layout (floats)
#define XS_STR    132                    // 33 x 16B (odd) -> conflict-free strided float4
#define XS_OFF    0                      // xs [49][132] = 6468
#define KV_STR    256                    // K: cols 0..127, V: cols 128..255 (all reads broadcast)
#define KV_OFF    6468                   // kv [49][256] = 12544
#define SCR_OFF   19012                  // wtile [128][64] = 8192  /  Q handoff [49][132] = 6468
#define Q_STR     132
#define SMEM_FLOATS (SCR_OFF + 8192)     // 27204 floats
#define SMEM_BYTES  (SMEM_FLOATS * 4)    // 108816 B

__device__ __forceinline__ void stage_tile64(float* scr, const float* w, int ldw, int cb, int tid)
{
    for (int u = tid; u < 128 * 16; u += 256) {
        int r = u >> 4, c = u & 15;
        reinterpret_cast<float4*>(scr + r * 64)[c] =
            reinterpret_cast<const float4*>(w + r * ldw + cb)[c];
    }
}

// 49x64 tile GEMM: warp owns 7 rows, lane owns 2 cols. x rows broadcast float4.
__device__ __forceinline__ void gemm_tile64(const float* __restrict__ xbase,
                                            const float* __restrict__ scr,
                                            int lane, float acc[7][2])
{
    #pragma unroll
    for (int r = 0; r < 7; ++r) { acc[r][0] = 0.f; acc[r][1] = 0.f; }
    const float* wcol = scr + lane * 2;
    #pragma unroll 2
    for (int k4 = 0; k4 < 32; ++k4) {
        float4 xv[7];
        #pragma unroll
        for (int r = 0; r < 7; ++r)
            xv[r] = reinterpret_cast<const float4*>(xbase + r * XS_STR)[k4];
        #pragma unroll
        for (int kk = 0; kk < 4; ++kk) {
            float2 w2 = *reinterpret_cast<const float2*>(wcol + (k4 * 4 + kk) * 64);
            #pragma unroll
            for (int r = 0; r < 7; ++r) {
                float xvk = (kk == 0) ? xv[r].x : (kk == 1) ? xv[r].y
                          : (kk == 2) ? xv[r].z : xv[r].w;
                acc[r][0] += xvk * w2.x;
                acc[r][1] += xvk * w2.y;
            }
        }
    }
}

__global__ __launch_bounds__(256, 2)
void swin_block_kernel(const float* __restrict__ x,
                       const float* __restrict__ w_qkv,
                       const float* __restrict__ b_qkv,
                       const float* __restrict__ w_proj,
                       const float* __restrict__ b_proj,
                       const float* __restrict__ rel_table,
                       float* __restrict__ out)
{
    extern __shared__ float smem[];
    float* xs  = smem + XS_OFF;   // input window, later attention output O
    float* kv  = smem + KV_OFF;   // K (0..127), V (128..255) per row
    float* scr = smem + SCR_OFF;  // weight tile / Q handoff
    __shared__ int lab[NTOK];

    const int tid  = threadIdx.x;
    const int warp = tid >> 5;
    const int lane = tid & 31;
    const int b    = blockIdx.x >> 6;
    const int widx = blockIdx.x & 63;
    const int wy   = widx >> 3;
    const int wx   = widx & 7;

    // ---------------- Phase 1: load rolled window + labels ----------------
    for (int t = tid; t < NTOK * 32; t += 256) {
        int n  = t >> 5, c4 = t & 31;
        int i  = n / 7, j = n - i * 7;
        int r  = wy * 7 + i + SHIFT; if (r  >= HWDIM) r  -= HWDIM;
        int cc = wx * 7 + j + SHIFT; if (cc >= HWDIM) cc -= HWDIM;
        const float4 v = reinterpret_cast<const float4*>(
            x + ((size_t)(b * HWDIM + r) * HWDIM + cc) * CCH)[c4];
        reinterpret_cast<float4*>(xs + n * XS_STR)[c4] = v;
    }
    if (tid < NTOK) {
        int i = tid / 7, j = tid - (tid / 7) * 7;
        int sh = wy * 7 + i, sw = wx * 7 + j;
        int rh = (sh < 49) ? 0 : ((sh < 53) ? 1 : 2);
        int rw = (sw < 49) ? 0 : ((sw < 53) ? 1 : 2);
        lab[tid] = rh * 3 + rw;
    }
    __syncthreads();

    // ---------------- Phase 2: QKV GEMM (K, V tiles -> smem; Q -> regs -> scr) ----------
    const float* xbase = xs + (warp < 7 ? warp : 0) * 7 * XS_STR;

    #pragma unroll 1
    for (int t = 0; t < 4; ++t) {               // K0 K1 V0 V1
        const int cb = 128 + (t << 6);
        stage_tile64(scr, w_qkv, 384, cb, tid);
        __syncthreads();
        if (warp < 7) {
            float acc[7][2];
            gemm_tile64(xbase, scr, lane, acc);
            float2 bb = *reinterpret_cast<const float2*>(b_qkv + cb + lane * 2);
            #pragma unroll
            for (int r = 0; r < 7; ++r) {
                float2 o; o.x = acc[r][0] + bb.x; o.y = acc[r][1] + bb.y;
                *reinterpret_cast<float2*>(
                    kv + (warp * 7 + r) * KV_STR + (cb - 128) + lane * 2) = o;
            }
        }
        __syncthreads();
    }

    float accQ0[7][2], accQ1[7][2];
    stage_tile64(scr, w_qkv, 384, 0, tid);
    __syncthreads();
    if (warp < 7) gemm_tile64(xbase, scr, lane, accQ0);
    __syncthreads();
    stage_tile64(scr, w_qkv, 384, 64, tid);
    __syncthreads();
    if (warp < 7) gemm_tile64(xbase, scr, lane, accQ1);
    __syncthreads();

    if (warp < 7) {                              // Q handoff (pre-scaled)
        float2 b0 = *reinterpret_cast<const float2*>(b_qkv + lane * 2);
        float2 b1 = *reinterpret_cast<const float2*>(b_qkv + 64 + lane * 2);
        #pragma unroll
        for (int r = 0; r < 7; ++r) {
            int row = warp * 7 + r;
            float2 o0, o1;
            o0.x = (accQ0[r][0] + b0.x) * SCALE; o0.y = (accQ0[r][1] + b0.y) * SCALE;
            o1.x = (accQ1[r][0] + b1.x) * SCALE; o1.y = (accQ1[r][1] + b1.y) * SCALE;
            *reinterpret_cast<float2*>(scr + row * Q_STR + lane * 2)      = o0;
            *reinterpret_cast<float2*>(scr + row * Q_STR + 64 + lane * 2) = o1;
        }
    }
    __syncthreads();

    // ---------------- Phase 3: attention, fully register-resident ----------------
    const int head = tid >> 6;            // 0..3
    const int lt   = tid & 63;
    const bool act = (lt < NTOK);
    const int i    = act ? lt : NTOK - 1;

    float4 q4[8];
    {
        const float4* qr = reinterpret_cast<const float4*>(scr + i * Q_STR + head * DH);
        #pragma unroll
        for (int m = 0; m < 8; ++m) q4[m] = qr[m];
    }

    float s[NTOK];
    {
        const float* kb = kv + head * DH;
        #pragma unroll
        for (int j = 0; j < NTOK; ++j) {
            const float4* kr = reinterpret_cast<const float4*>(kb + j * KV_STR);
            float a = 0.f;
            #pragma unroll
            for (int m = 0; m < 8; ++m) {
                float4 k4 = kr[m];   // broadcast
                a += q4[m].x * k4.x + q4[m].y * k4.y + q4[m].z * k4.z + q4[m].w * k4.w;
            }
            s[j] = a;
        }
    }

    float mx = s[0];
    #pragma unroll
    for (int j = 1; j < NTOK; ++j) mx = fmaxf(mx, s[j]);
    float sum = 0.f;
    #pragma unroll
    for (int j = 0; j < NTOK; ++j) { s[j] = __expf(s[j] - mx); sum += s[j]; }
    const float inv = 1.f / sum;

    {
        const int yi = i / 7, xi = i - 7 * (i / 7);
        const int li = lab[i];
        #pragma unroll
        for (int j = 0; j < NTOK; ++j) {
            int yj = j / 7, xj = j - 7 * yj;
            float bias = __ldg(rel_table + ((yi - yj + 6) * 13 + (xi - xj + 6)) * NH + head);
            float mk = (lab[j] != li) ? -100.f : 0.f;
            s[j] = s[j] * inv + bias + mk;
        }
    }

    {
        float oacc[32];
        #pragma unroll
        for (int d = 0; d < 32; ++d) oacc[d] = 0.f;
        const float* vb = kv + 128 + head * DH;
        #pragma unroll
        for (int j = 0; j < NTOK; ++j) {
            float a = s[j];
            const float4* vr = reinterpret_cast<const float4*>(vb + j * KV_STR);
            #pragma unroll
            for (int m = 0; m < 8; ++m) {
                float4 v4 = vr[m];   // broadcast
                oacc[4 * m + 0] += a * v4.x;
                oacc[4 * m + 1] += a * v4.y;
                oacc[4 * m + 2] += a * v4.z;
                oacc[4 * m + 3] += a * v4.w;
            }
        }
        if (act) {
            float4* dst = reinterpret_cast<float4*>(xs + i * XS_STR + head * DH);
            #pragma unroll
            for (int m = 0; m < 8; ++m)
                dst[m] = make_float4(oacc[4 * m], oacc[4 * m + 1],
                                     oacc[4 * m + 2], oacc[4 * m + 3]);
        }
    }
    __syncthreads();

    // ---------------- Phase 4: proj GEMM + window-reverse + roll-back write ----------
    #pragma unroll 1
    for (int t = 0; t < 2; ++t) {
        const int cb = t << 6;
        stage_tile64(scr, w_proj, 128, cb, tid);
        __syncthreads();
        if (warp < 7) {
            float acc[7][2];
            gemm_tile64(xbase, scr, lane, acc);
            float2 bb = *reinterpret_cast<const float2*>(b_proj + cb + lane * 2);
            int rg = wy * 7 + warp + SHIFT; if (rg >= HWDIM) rg -= HWDIM;
            #pragma unroll
            for (int r = 0; r < 7; ++r) {
                int cg = wx * 7 + r + SHIFT; if (cg >= HWDIM) cg -= HWDIM;
                float2 o; o.x = acc[r][0] + bb.x; o.y = acc[r][1] + bb.y;
                *reinterpret_cast<float2*>(
                    out + ((size_t)(b * HWDIM + rg) * HWDIM + cg) * CCH + cb + lane * 2) = o;
            }
        }
        __syncthreads();
    }
}

extern "C" void kernel_launch(void* const* d_in, const int* in_sizes, int n_in,
                              void* d_out, int out_size)
{
    const float* x         = (const float*)d_in[0];
    const float* w_qkv     = (const float*)d_in[1];
    const float* b_qkv     = (const float*)d_in[2];
    const float* w_proj    = (const float*)d_in[3];
    const float* b_proj    = (const float*)d_in[4];
    const float* rel_table = (const float*)d_in[5];
    float* out = (float*)d_out;

    cudaFuncSetAttribute(swin_block_kernel,
                         cudaFuncAttributeMaxDynamicSharedMemorySize, SMEM_BYTES);

    dim3 grid(64 * 64);
    dim3 block(256);
    swin_block_kernel<<<grid, block, SMEM_BYTES>>>(
        x, w_qkv, b_qkv, w_proj, b_proj, rel_table, out);
}

// round 7
// speedup vs baseline: 1.9399x; 1.0001x over previous
#include <cuda_runtime.h>
#include <cstdint>

#define NTOK      49
#define CCH       128
#define NH        4
#define DH        32
#define HWDIM     56
#define SHIFT     3
#define SCALE     0.17677669529663687f   // 32^-0.5

// dynamic shared memory layout (floats)
#define XS_STR    132                    // 33 x 16B (odd) -> conflict-free strided float4
#define XS_OFF    0                      // xs [49][132] = 6468
#define KV_STR    256                    // K: cols 0..127, V: cols 128..255 (all reads broadcast)
#define KV_OFF    6468                   // kv [49][256] = 12544
#define SCR_OFF   19012                  // wtile [128][64] = 8192  /  Q handoff [49][132] = 6468
#define Q_STR     132
#define SMEM_FLOATS (SCR_OFF + 8192)     // 27204 floats
#define SMEM_BYTES  (SMEM_FLOATS * 4)    // 108816 B

__device__ __forceinline__ void stage_tile64(float* scr, const float* w, int ldw, int cb, int tid)
{
    for (int u = tid; u < 128 * 16; u += 256) {
        int r = u >> 4, c = u & 15;
        reinterpret_cast<float4*>(scr + r * 64)[c] =
            reinterpret_cast<const float4*>(w + r * ldw + cb)[c];
    }
}

// 49x64 tile GEMM: warp owns 7 rows, lane owns 2 cols. x rows broadcast float4.
__device__ __forceinline__ void gemm_tile64(const float* __restrict__ xbase,
                                            const float* __restrict__ scr,
                                            int lane, float acc[7][2])
{
    #pragma unroll
    for (int r = 0; r < 7; ++r) { acc[r][0] = 0.f; acc[r][1] = 0.f; }
    const float* wcol = scr + lane * 2;
    #pragma unroll 2
    for (int k4 = 0; k4 < 32; ++k4) {
        float4 xv[7];
        #pragma unroll
        for (int r = 0; r < 7; ++r)
            xv[r] = reinterpret_cast<const float4*>(xbase + r * XS_STR)[k4];
        #pragma unroll
        for (int kk = 0; kk < 4; ++kk) {
            float2 w2 = *reinterpret_cast<const float2*>(wcol + (k4 * 4 + kk) * 64);
            #pragma unroll
            for (int r = 0; r < 7; ++r) {
                float xvk = (kk == 0) ? xv[r].x : (kk == 1) ? xv[r].y
                          : (kk == 2) ? xv[r].z : xv[r].w;
                acc[r][0] += xvk * w2.x;
                acc[r][1] += xvk * w2.y;
            }
        }
    }
}

__global__ __launch_bounds__(256, 2)
void swin_block_kernel(const float* __restrict__ x,
                       const float* __restrict__ w_qkv,
                       const float* __restrict__ b_qkv,
                       const float* __restrict__ w_proj,
                       const float* __restrict__ b_proj,
                       const float* __restrict__ rel_table,
                       float* __restrict__ out)
{
    extern __shared__ float smem[];
    float* xs  = smem + XS_OFF;   // input window, later attention output O
    float* kv  = smem + KV_OFF;   // K (0..127), V (128..255) per row
    float* scr = smem + SCR_OFF;  // weight tile / Q handoff
    __shared__ int lab[NTOK];

    const int tid  = threadIdx.x;
    const int warp = tid >> 5;
    const int lane = tid & 31;
    const int b    = blockIdx.x >> 6;
    const int widx = blockIdx.x & 63;
    const int wy   = widx >> 3;
    const int wx   = widx & 7;

    // ---------------- Phase 1: load rolled window + labels ----------------
    for (int t = tid; t < NTOK * 32; t += 256) {
        int n  = t >> 5, c4 = t & 31;
        int i  = n / 7, j = n - i * 7;
        int r  = wy * 7 + i + SHIFT; if (r  >= HWDIM) r  -= HWDIM;
        int cc = wx * 7 + j + SHIFT; if (cc >= HWDIM) cc -= HWDIM;
        const float4 v = reinterpret_cast<const float4*>(
            x + ((size_t)(b * HWDIM + r) * HWDIM + cc) * CCH)[c4];
        reinterpret_cast<float4*>(xs + n * XS_STR)[c4] = v;
    }
    if (tid < NTOK) {
        int i = tid / 7, j = tid - (tid / 7) * 7;
        int sh = wy * 7 + i, sw = wx * 7 + j;
        int rh = (sh < 49) ? 0 : ((sh < 53) ? 1 : 2);
        int rw = (sw < 49) ? 0 : ((sw < 53) ? 1 : 2);
        lab[tid] = rh * 3 + rw;
    }
    __syncthreads();

    // ---------------- Phase 2: QKV GEMM (K, V tiles -> smem; Q -> regs -> scr) ----------
    const float* xbase = xs + (warp < 7 ? warp : 0) * 7 * XS_STR;

    #pragma unroll 1
    for (int t = 0; t < 4; ++t) {               // K0 K1 V0 V1
        const int cb = 128 + (t << 6);
        stage_tile64(scr, w_qkv, 384, cb, tid);
        __syncthreads();
        if (warp < 7) {
            float acc[7][2];
            gemm_tile64(xbase, scr, lane, acc);
            float2 bb = *reinterpret_cast<const float2*>(b_qkv + cb + lane * 2);
            #pragma unroll
            for (int r = 0; r < 7; ++r) {
                float2 o; o.x = acc[r][0] + bb.x; o.y = acc[r][1] + bb.y;
                *reinterpret_cast<float2*>(
                    kv + (warp * 7 + r) * KV_STR + (cb - 128) + lane * 2) = o;
            }
        }
        __syncthreads();
    }

    float accQ0[7][2], accQ1[7][2];
    stage_tile64(scr, w_qkv, 384, 0, tid);
    __syncthreads();
    if (warp < 7) gemm_tile64(xbase, scr, lane, accQ0);
    __syncthreads();
    stage_tile64(scr, w_qkv, 384, 64, tid);
    __syncthreads();
    if (warp < 7) gemm_tile64(xbase, scr, lane, accQ1);
    __syncthreads();

    if (warp < 7) {                              // Q handoff (pre-scaled)
        float2 b0 = *reinterpret_cast<const float2*>(b_qkv + lane * 2);
        float2 b1 = *reinterpret_cast<const float2*>(b_qkv + 64 + lane * 2);
        #pragma unroll
        for (int r = 0; r < 7; ++r) {
            int row = warp * 7 + r;
            float2 o0, o1;
            o0.x = (accQ0[r][0] + b0.x) * SCALE; o0.y = (accQ0[r][1] + b0.y) * SCALE;
            o1.x = (accQ1[r][0] + b1.x) * SCALE; o1.y = (accQ1[r][1] + b1.y) * SCALE;
            *reinterpret_cast<float2*>(scr + row * Q_STR + lane * 2)      = o0;
            *reinterpret_cast<float2*>(scr + row * Q_STR + 64 + lane * 2) = o1;
        }
    }
    __syncthreads();

    // ---------------- Phase 3: attention, fully register-resident ----------------
    const int head = tid >> 6;            // 0..3
    const int lt   = tid & 63;
    const bool act = (lt < NTOK);
    const int i    = act ? lt : NTOK - 1;

    float4 q4[8];
    {
        const float4* qr = reinterpret_cast<const float4*>(scr + i * Q_STR + head * DH);
        #pragma unroll
        for (int m = 0; m < 8; ++m) q4[m] = qr[m];
    }

    float s[NTOK];
    {
        const float* kb = kv + head * DH;
        #pragma unroll
        for (int j = 0; j < NTOK; ++j) {
            const float4* kr = reinterpret_cast<const float4*>(kb + j * KV_STR);
            float a = 0.f;
            #pragma unroll
            for (int m = 0; m < 8; ++m) {
                float4 k4 = kr[m];   // broadcast
                a += q4[m].x * k4.x + q4[m].y * k4.y + q4[m].z * k4.z + q4[m].w * k4.w;
            }
            s[j] = a;
        }
    }

    float mx = s[0];
    #pragma unroll
    for (int j = 1; j < NTOK; ++j) mx = fmaxf(mx, s[j]);
    float sum = 0.f;
    #pragma unroll
    for (int j = 0; j < NTOK; ++j) { s[j] = __expf(s[j] - mx); sum += s[j]; }
    const float inv = 1.f / sum;

    {
        const int yi = i / 7, xi = i - 7 * (i / 7);
        const int li = lab[i];
        #pragma unroll
        for (int j = 0; j < NTOK; ++j) {
            int yj = j / 7, xj = j - 7 * yj;
            float bias = __ldg(rel_table + ((yi - yj + 6) * 13 + (xi - xj + 6)) * NH + head);
            float mk = (lab[j] != li) ? -100.f : 0.f;
            s[j] = s[j] * inv + bias + mk;
        }
    }

    {
        float oacc[32];
        #pragma unroll
        for (int d = 0; d < 32; ++d) oacc[d] = 0.f;
        const float* vb = kv + 128 + head * DH;
        #pragma unroll
        for (int j = 0; j < NTOK; ++j) {
            float a = s[j];
            const float4* vr = reinterpret_cast<const float4*>(vb + j * KV_STR);
            #pragma unroll
            for (int m = 0; m < 8; ++m) {
                float4 v4 = vr[m];   // broadcast
                oacc[4 * m + 0] += a * v4.x;
                oacc[4 * m + 1] += a * v4.y;
                oacc[4 * m + 2] += a * v4.z;
                oacc[4 * m + 3] += a * v4.w;
            }
        }
        if (act) {
            float4* dst = reinterpret_cast<float4*>(xs + i * XS_STR + head * DH);
            #pragma unroll
            for (int m = 0; m < 8; ++m)
                dst[m] = make_float4(oacc[4 * m], oacc[4 * m + 1],
                                     oacc[4 * m + 2], oacc[4 * m + 3]);
        }
    }
    __syncthreads();

    // ---------------- Phase 4: proj GEMM + window-reverse + roll-back write ----------
    #pragma unroll 1
    for (int t = 0; t < 2; ++t) {
        const int cb = t << 6;
        stage_tile64(scr, w_proj, 128, cb, tid);
        __syncthreads();
        if (warp < 7) {
            float acc[7][2];
            gemm_tile64(xbase, scr, lane, acc);
            float2 bb = *reinterpret_cast<const float2*>(b_proj + cb + lane * 2);
            int rg = wy * 7 + warp + SHIFT; if (rg >= HWDIM) rg -= HWDIM;
            #pragma unroll
            for (int r = 0; r < 7; ++r) {
                int cg = wx * 7 + r + SHIFT; if (cg >= HWDIM) cg -= HWDIM;
                float2 o; o.x = acc[r][0] + bb.x; o.y = acc[r][1] + bb.y;
                *reinterpret_cast<float2*>(
                    out + ((size_t)(b * HWDIM + rg) * HWDIM + cg) * CCH + cb + lane * 2) = o;
            }
        }
        __syncthreads();
    }
}

extern "C" void kernel_launch(void* const* d_in, const int* in_sizes, int n_in,
                              void* d_out, int out_size)
{
    const float* x         = (const float*)d_in[0];
    const float* w_qkv     = (const float*)d_in[1];
    const float* b_qkv     = (const float*)d_in[2];
    const float* w_proj    = (const float*)d_in[3];
    const float* b_proj    = (const float*)d_in[4];
    const float* rel_table = (const float*)d_in[5];
    float* out = (float*)d_out;

    cudaFuncSetAttribute(swin_block_kernel,
                         cudaFuncAttributeMaxDynamicSharedMemorySize, SMEM_BYTES);

    dim3 grid(64 * 64);
    dim3 block(256);
    swin_block_kernel<<<grid, block, SMEM_BYTES>>>(
        x, w_qkv, b_qkv, w_proj, b_proj, rel_table, out);
}

// round 11
// speedup vs baseline: 2.5516x; 1.3153x over previous
#include <cuda_runtime.h>
#include <cuda_fp16.h>
#include <mma.h>
#include <cstdint>

using namespace nvcuda;

#define NTOK   49
#define CCH    128
#define NH     4
#define DH     32
#define HWDIM  56
#define SHIFT  3
#define SCALE  0.17677669529663687f

// smem layout (float offsets) — every WMMA region base and row pitch 32B-aligned
#define A_LO_OFF  4352          // a_hi halves at float 0 (4352 floats = 8704 halves)
#define Q_OFF     8704          // [49][136] fp32 (+benign spill into KV region)
#define Q_STR     136           // 544 B row pitch (17x32)
#define KV_OFF    15368         // [49][264] fp32: K cols 0..127, V 128..255 (+spill into BH)
#define KV_STR    264           // 1056 B row pitch (33x32)
#define BH_OFF    28304         // staged B hi: 128x136 halves = 8704 floats
#define BL_OFF    37008
#define SMEM_FLOATS 45712
#define SMEM_BYTES  (SMEM_FLOATS * 4)   // 182848 B
#define AH_STR 136              // half stride (272 B rows, 16B-aligned for ldmatrix)

typedef wmma::fragment<wmma::matrix_a, 16, 16, 16, __half, wmma::row_major> FragA;
typedef wmma::fragment<wmma::matrix_b, 16, 16, 16, __half, wmma::row_major> FragB;
typedef wmma::fragment<wmma::accumulator, 16, 16, 16, float> FragC;

// prepped weights: [4 tiles][128k x 136n] halves (tiles 0..2 = qkv cols t*128.., 3 = proj)
__device__ __align__(16) __half g_bhi[4][128 * 136];
__device__ __align__(16) __half g_blo[4][128 * 136];

__global__ void prep_kernel(const float* __restrict__ w_qkv, const float* __restrict__ w_proj)
{
    int idx = blockIdx.x * 256 + threadIdx.x;
    if (idx >= 4 * 128 * 136) return;
    int t = idx / (128 * 136), rem = idx % (128 * 136);
    int k = rem / 136, n = rem % 136;
    float v = 0.f;
    if (n < 128) v = (t < 3) ? w_qkv[k * 384 + t * 128 + n] : w_proj[k * 128 + n];
    __half h = __float2half_rn(v);
    g_bhi[t][k * 136 + n] = h;
    g_blo[t][k * 136 + n] = __float2half_rn(v - __half2float(h));
}

__global__ __launch_bounds__(256, 1)
void swin_block_kernel(const float* __restrict__ x,
                       const float* __restrict__ b_qkv,
                       const float* __restrict__ b_proj,
                       const float* __restrict__ rel_table,
                       float* __restrict__ out)
{
    extern __shared__ float smem[];
    __shared__ int lab[NTOK];

    __half* aHI = reinterpret_cast<__half*>(smem);
    __half* aLO = reinterpret_cast<__half*>(smem + A_LO_OFF);
    const __half* bHI = reinterpret_cast<const __half*>(smem + BH_OFF);
    const __half* bLO = reinterpret_cast<const __half*>(smem + BL_OFF);

    const int tid = threadIdx.x, warp = tid >> 5;
    const int b = blockIdx.x >> 6, widx = blockIdx.x & 63;
    const int wy = widx >> 3, wx = widx & 7;
    const int mi0 = (warp >> 2) * 2;     // {0,2}
    const int ni0 = (warp & 3) * 2;      // {0,2,4,6}

    // ---------------- Phase 1: rolled window -> hi/lo halves; labels; zero pad rows ----
    for (int t = tid; t < NTOK * 32; t += 256) {
        int n = t >> 5, c4 = t & 31, i = n / 7, j = n - i * 7;
        int r  = wy * 7 + i + SHIFT; if (r  >= HWDIM) r  -= HWDIM;
        int cc = wx * 7 + j + SHIFT; if (cc >= HWDIM) cc -= HWDIM;
        float4 v = reinterpret_cast<const float4*>(
            x + ((size_t)(b * HWDIM + r) * HWDIM + cc) * CCH)[c4];
        __half h0 = __float2half_rn(v.x), h1 = __float2half_rn(v.y);
        __half h2 = __float2half_rn(v.z), h3 = __float2half_rn(v.w);
        __half2* ph = reinterpret_cast<__half2*>(aHI + n * AH_STR + c4 * 4);
        ph[0] = __halves2half2(h0, h1); ph[1] = __halves2half2(h2, h3);
        __half2* pl = reinterpret_cast<__half2*>(aLO + n * AH_STR + c4 * 4);
        pl[0] = __floats2half2_rn(v.x - __half2float(h0), v.y - __half2float(h1));
        pl[1] = __floats2half2_rn(v.z - __half2float(h2), v.w - __half2float(h3));
    }
    for (int t = tid; t < 15 * AH_STR; t += 256) {   // zero rows 49..63
        int r = 49 + t / AH_STR, c = t % AH_STR;
        aHI[r * AH_STR + c] = __ushort_as_half(0);
        aLO[r * AH_STR + c] = __ushort_as_half(0);
    }
    if (tid < NTOK) {
        int i = tid / 7, j = tid - (tid / 7) * 7;
        int sh = wy * 7 + i, sw = wx * 7 + j;
        lab[tid] = ((sh < 49) ? 0 : (sh < 53) ? 1 : 2) * 3 + ((sw < 49) ? 0 : (sw < 53) ? 1 : 2);
    }
    __syncthreads();

    // ---------------- Phase 2: QKV GEMM via WMMA, 3 chunks of 128 cols ----------------
    #pragma unroll 1
    for (int t = 0; t < 3; ++t) {
        {   // stage B tile t (8704 floats = 2176 uint4)
            const uint4* sh = reinterpret_cast<const uint4*>(g_bhi[t]);
            const uint4* sl = reinterpret_cast<const uint4*>(g_blo[t]);
            uint4* dh = reinterpret_cast<uint4*>(smem + BH_OFF);
            uint4* dl = reinterpret_cast<uint4*>(smem + BL_OFF);
            for (int u = tid; u < 2176; u += 256) { dh[u] = sh[u]; dl[u] = sl[u]; }
        }
        __syncthreads();

        FragC c[2][2];
        #pragma unroll
        for (int a = 0; a < 2; ++a)
            #pragma unroll
            for (int d = 0; d < 2; ++d) wmma::fill_fragment(c[a][d], 0.f);

        #pragma unroll 1
        for (int k = 0; k < 8; ++k) {
            FragA ahi[2], alo[2];
            FragB bhi[2], blo[2];
            #pragma unroll
            for (int a = 0; a < 2; ++a) {
                wmma::load_matrix_sync(ahi[a], aHI + (mi0 + a) * 16 * AH_STR + k * 16, AH_STR);
                wmma::load_matrix_sync(alo[a], aLO + (mi0 + a) * 16 * AH_STR + k * 16, AH_STR);
            }
            #pragma unroll
            for (int d = 0; d < 2; ++d) {
                wmma::load_matrix_sync(bhi[d], bHI + k * 16 * AH_STR + (ni0 + d) * 16, AH_STR);
                wmma::load_matrix_sync(blo[d], bLO + k * 16 * AH_STR + (ni0 + d) * 16, AH_STR);
            }
            #pragma unroll
            for (int a = 0; a < 2; ++a)
                #pragma unroll
                for (int d = 0; d < 2; ++d) {
                    wmma::mma_sync(c[a][d], ahi[a], bhi[d], c[a][d]);
                    wmma::mma_sync(c[a][d], ahi[a], blo[d], c[a][d]);
                    wmma::mma_sync(c[a][d], alo[a], bhi[d], c[a][d]);
                }
        }
        __syncthreads();   // all mma done before stores spill into BH region

        float* dst = (t == 0) ? (smem + Q_OFF) : (smem + KV_OFF + (t - 1) * 128);
        const int ld = (t == 0) ? Q_STR : KV_STR;
        #pragma unroll
        for (int a = 0; a < 2; ++a)
            #pragma unroll
            for (int d = 0; d < 2; ++d)
                wmma::store_matrix_sync(dst + (mi0 + a) * 16 * ld + (ni0 + d) * 16,
                                        c[a][d], ld, wmma::mem_row_major);
        __syncthreads();
    }

    // bias (+scale for Q)
    for (int u = tid; u < NTOK * 128; u += 256) {
        int r = u >> 7, cc = u & 127;
        float* qp = smem + Q_OFF + r * Q_STR + cc;
        *qp = (*qp + b_qkv[cc]) * SCALE;
    }
    for (int u = tid; u < NTOK * 256; u += 256) {
        int r = u >> 8, cc = u & 255;
        float* kp = smem + KV_OFF + r * KV_STR + cc;
        *kp += b_qkv[128 + cc];
    }
    __syncthreads();

    // ---------------- Phase 3: attention (fp32 regs; bias+mask AFTER softmax) ---------
    {
        const int head = tid >> 6, lt = tid & 63;
        const bool act = (lt < NTOK);
        const int i = act ? lt : NTOK - 1;
        const float* qsm = smem + Q_OFF;
        const float* kv  = smem + KV_OFF;

        float4 q4[8];
        const float4* qr = reinterpret_cast<const float4*>(qsm + i * Q_STR + head * DH);
        #pragma unroll
        for (int m = 0; m < 8; ++m) q4[m] = qr[m];

        float s[NTOK];
        const float* kb = kv + head * DH;
        #pragma unroll
        for (int j = 0; j < NTOK; ++j) {
            const float4* kr = reinterpret_cast<const float4*>(kb + j * KV_STR);
            float a = 0.f;
            #pragma unroll
            for (int m = 0; m < 8; ++m) {
                float4 k4 = kr[m];
                a += q4[m].x * k4.x + q4[m].y * k4.y + q4[m].z * k4.z + q4[m].w * k4.w;
            }
            s[j] = a;
        }
        float mx = s[0];
        #pragma unroll
        for (int j = 1; j < NTOK; ++j) mx = fmaxf(mx, s[j]);
        float sum = 0.f;
        #pragma unroll
        for (int j = 0; j < NTOK; ++j) { s[j] = __expf(s[j] - mx); sum += s[j]; }
        const float inv = 1.f / sum;
        const int yi = i / 7, xi = i - 7 * (i / 7), li = lab[i];
        #pragma unroll
        for (int j = 0; j < NTOK; ++j) {
            int yj = j / 7, xj = j - 7 * yj;
            float bias = __ldg(rel_table + ((yi - yj + 6) * 13 + (xi - xj + 6)) * NH + head);
            s[j] = s[j] * inv + bias + ((lab[j] != li) ? -100.f : 0.f);
        }
        float oa[32];
        #pragma unroll
        for (int d = 0; d < 32; ++d) oa[d] = 0.f;
        const float* vb = kv + 128 + head * DH;
        #pragma unroll
        for (int j = 0; j < NTOK; ++j) {
            float a = s[j];
            const float4* vr = reinterpret_cast<const float4*>(vb + j * KV_STR);
            #pragma unroll
            for (int m = 0; m < 8; ++m) {
                float4 v4 = vr[m];
                oa[4*m] += a*v4.x; oa[4*m+1] += a*v4.y; oa[4*m+2] += a*v4.z; oa[4*m+3] += a*v4.w;
            }
        }
        __syncthreads();   // a_hi/a_lo no longer read by anyone
        if (act) {
            #pragma unroll
            for (int m = 0; m < 8; ++m) {
                float vx = oa[4*m], vy = oa[4*m+1], vz = oa[4*m+2], vw = oa[4*m+3];
                __half h0 = __float2half_rn(vx), h1 = __float2half_rn(vy);
                __half h2 = __float2half_rn(vz), h3 = __float2half_rn(vw);
                __half2* ph = reinterpret_cast<__half2*>(aHI + i * AH_STR + head * DH + 4 * m);
                ph[0] = __halves2half2(h0, h1); ph[1] = __halves2half2(h2, h3);
                __half2* pl = reinterpret_cast<__half2*>(aLO + i * AH_STR + head * DH + 4 * m);
                pl[0] = __floats2half2_rn(vx - __half2float(h0), vy - __half2float(h1));
                pl[1] = __floats2half2_rn(vz - __half2float(h2), vw - __half2float(h3));
            }
        }
    }
    __syncthreads();

    // ---------------- Phase 4: proj GEMM (tile 3) -> Q buffer -> scatter ----------------
    {
        const uint4* sh = reinterpret_cast<const uint4*>(g_bhi[3]);
        const uint4* sl = reinterpret_cast<const uint4*>(g_blo[3]);
        uint4* dh = reinterpret_cast<uint4*>(smem + BH_OFF);
        uint4* dl = reinterpret_cast<uint4*>(smem + BL_OFF);
        for (int u = tid; u < 2176; u += 256) { dh[u] = sh[u]; dl[u] = sl[u]; }
    }
    __syncthreads();
    {
        FragC c[2][2];
        #pragma unroll
        for (int a = 0; a < 2; ++a)
            #pragma unroll
            for (int d = 0; d < 2; ++d) wmma::fill_fragment(c[a][d], 0.f);
        #pragma unroll 1
        for (int k = 0; k < 8; ++k) {
            FragA ahi[2], alo[2];
            FragB bhi[2], blo[2];
            #pragma unroll
            for (int a = 0; a < 2; ++a) {
                wmma::load_matrix_sync(ahi[a], aHI + (mi0 + a) * 16 * AH_STR + k * 16, AH_STR);
                wmma::load_matrix_sync(alo[a], aLO + (mi0 + a) * 16 * AH_STR + k * 16, AH_STR);
            }
            #pragma unroll
            for (int d = 0; d < 2; ++d) {
                wmma::load_matrix_sync(bhi[d], bHI + k * 16 * AH_STR + (ni0 + d) * 16, AH_STR);
                wmma::load_matrix_sync(blo[d], bLO + k * 16 * AH_STR + (ni0 + d) * 16, AH_STR);
            }
            #pragma unroll
            for (int a = 0; a < 2; ++a)
                #pragma unroll
                for (int d = 0; d < 2; ++d) {
                    wmma::mma_sync(c[a][d], ahi[a], bhi[d], c[a][d]);
                    wmma::mma_sync(c[a][d], ahi[a], blo[d], c[a][d]);
                    wmma::mma_sync(c[a][d], alo[a], bhi[d], c[a][d]);
                }
        }
        __syncthreads();
        #pragma unroll
        for (int a = 0; a < 2; ++a)
            #pragma unroll
            for (int d = 0; d < 2; ++d)
                wmma::store_matrix_sync(smem + Q_OFF + (mi0 + a) * 16 * Q_STR + (ni0 + d) * 16,
                                        c[a][d], Q_STR, wmma::mem_row_major);
    }
    __syncthreads();

    // scatter: window-reverse + roll + bias
    for (int t = tid; t < NTOK * 32; t += 256) {
        int n = t >> 5, c4 = t & 31, i = n / 7, j = n - i * 7;
        int rg = wy * 7 + i + SHIFT; if (rg >= HWDIM) rg -= HWDIM;
        int cg = wx * 7 + j + SHIFT; if (cg >= HWDIM) cg -= HWDIM;
        float4 v  = reinterpret_cast<const float4*>(smem + Q_OFF + n * Q_STR)[c4];
        float4 bb = reinterpret_cast<const float4*>(b_proj)[c4];
        v.x += bb.x; v.y += bb.y; v.z += bb.z; v.w += bb.w;
        reinterpret_cast<float4*>(
            out + ((size_t)(b * HWDIM + rg) * HWDIM + cg) * CCH)[c4] = v;
    }
}

extern "C" void kernel_launch(void* const* d_in, const int* in_sizes, int n_in,
                              void* d_out, int out_size)
{
    const float* x         = (const float*)d_in[0];
    const float* w_qkv     = (const float*)d_in[1];
    const float* b_qkv     = (const float*)d_in[2];
    const float* w_proj    = (const float*)d_in[3];
    const float* b_proj    = (const float*)d_in[4];
    const float* rel_table = (const float*)d_in[5];
    float* out = (float*)d_out;

    cudaFuncSetAttribute(swin_block_kernel,
                         cudaFuncAttributeMaxDynamicSharedMemorySize, SMEM_BYTES);
    prep_kernel<<<(4 * 128 * 136 + 255) / 256, 256>>>(w_qkv, w_proj);
    swin_block_kernel<<<4096, 256, SMEM_BYTES>>>(x, b_qkv, b_proj, rel_table, out);
}

// round 13
// speedup vs baseline: 3.1884x; 1.2496x over previous
#include <cuda_runtime.h>
#include <cuda_fp16.h>
#include <mma.h>
#include <cstdint>

using namespace nvcuda;

#define NTOK   49
#define CCH    128
#define NH     4
#define DH     32
#define HWDIM  56
#define SHIFT  3
#define SCALE  0.17677669529663687f

// smem layout (float offsets), all WMMA bases/strides 32B-aligned
// AV region [0,8704): aHI halves (0..4352 fl), aLO halves (4352..8704 fl); later V fp32 [64][136]
#define A_LO_OFF  4352
#define AH_STR    136          // halves
#define V_STR     136          // floats
#define Q_OFF     8704         // [49][136] fp32 (spill rows 49-63 -> K region, overwritten)
#define Q_STR     136
#define K_OFF     15368        // [64][136] fp32 (incl spill rows)
#define K_STR     136
#define SMEM_FLOATS 24072
#define SMEM_BYTES  (SMEM_FLOATS * 4)   // 96288 B -> 2 CTAs/SM
#define BW_STR 136             // global prepped weight stride (halves)

typedef wmma::fragment<wmma::matrix_a, 16, 16, 16, __half, wmma::row_major> FragA;
typedef wmma::fragment<wmma::matrix_b, 16, 16, 16, __half, wmma::row_major> FragB;
typedef wmma::fragment<wmma::accumulator, 16, 16, 16, float> FragC;

// prepped weights: [4 tiles][128k x 136n] halves (tiles 0..2 = qkv cols t*128.., 3 = proj)
__device__ __align__(16) __half g_bhi[4][128 * 136];
__device__ __align__(16) __half g_blo[4][128 * 136];

__global__ void prep_kernel(const float* __restrict__ w_qkv, const float* __restrict__ w_proj)
{
    int idx = blockIdx.x * 256 + threadIdx.x;
    if (idx >= 4 * 128 * 136) return;
    int t = idx / (128 * 136), rem = idx % (128 * 136);
    int k = rem / 136, n = rem % 136;
    float v = 0.f;
    if (n < 128) v = (t < 3) ? w_qkv[k * 384 + t * 128 + n] : w_proj[k * 128 + n];
    __half h = __float2half_rn(v);
    g_bhi[t][k * 136 + n] = h;
    g_blo[t][k * 136 + n] = __float2half_rn(v - __half2float(h));
}

__global__ __launch_bounds__(256, 2)
void swin_block_kernel(const float* __restrict__ x,
                       const float* __restrict__ b_qkv,
                       const float* __restrict__ b_proj,
                       const float* __restrict__ rel_table,
                       float* __restrict__ out)
{
    extern __shared__ float smem[];
    __shared__ int lab[NTOK];

    __half* aHI = reinterpret_cast<__half*>(smem);
    __half* aLO = reinterpret_cast<__half*>(smem + A_LO_OFF);

    const int tid = threadIdx.x, warp = tid >> 5;
    const int b = blockIdx.x >> 6, widx = blockIdx.x & 63;
    const int wy = widx >> 3, wx = widx & 7;
    const int mi0 = (warp >> 2) * 2;     // {0,2}
    const int ni0 = (warp & 3) * 2;      // {0,2,4,6}

    // ---------------- Phase 1: rolled window -> hi/lo halves; labels; zero pad rows ----
    for (int t = tid; t < NTOK * 32; t += 256) {
        int n = t >> 5, c4 = t & 31, i = n / 7, j = n - i * 7;
        int r  = wy * 7 + i + SHIFT; if (r  >= HWDIM) r  -= HWDIM;
        int cc = wx * 7 + j + SHIFT; if (cc >= HWDIM) cc -= HWDIM;
        float4 v = reinterpret_cast<const float4*>(
            x + ((size_t)(b * HWDIM + r) * HWDIM + cc) * CCH)[c4];
        __half h0 = __float2half_rn(v.x), h1 = __float2half_rn(v.y);
        __half h2 = __float2half_rn(v.z), h3 = __float2half_rn(v.w);
        __half2* ph = reinterpret_cast<__half2*>(aHI + n * AH_STR + c4 * 4);
        ph[0] = __halves2half2(h0, h1); ph[1] = __halves2half2(h2, h3);
        __half2* pl = reinterpret_cast<__half2*>(aLO + n * AH_STR + c4 * 4);
        pl[0] = __floats2half2_rn(v.x - __half2float(h0), v.y - __half2float(h1));
        pl[1] = __floats2half2_rn(v.z - __half2float(h2), v.w - __half2float(h3));
    }
    for (int t = tid; t < 15 * AH_STR; t += 256) {   // zero rows 49..63
        int r = 49 + t / AH_STR, c = t % AH_STR;
        aHI[r * AH_STR + c] = __ushort_as_half(0);
        aLO[r * AH_STR + c] = __ushort_as_half(0);
    }
    if (tid < NTOK) {
        int i = tid / 7, j = tid - (tid / 7) * 7;
        int sh = wy * 7 + i, sw = wx * 7 + j;
        lab[tid] = ((sh < 49) ? 0 : (sh < 53) ? 1 : 2) * 3 + ((sw < 49) ? 0 : (sw < 53) ? 1 : 2);
    }
    __syncthreads();

    // ---------------- Phase 2: QKV GEMM via WMMA; B fragments direct from global -----
    #pragma unroll 1
    for (int t = 0; t < 3; ++t) {
        const __half* gbh = g_bhi[t];
        const __half* gbl = g_blo[t];

        FragC c[2][2];
        #pragma unroll
        for (int a = 0; a < 2; ++a)
            #pragma unroll
            for (int d = 0; d < 2; ++d) wmma::fill_fragment(c[a][d], 0.f);

        #pragma unroll 1
        for (int k = 0; k < 8; ++k) {
            FragA ahi[2], alo[2];
            FragB bhi[2], blo[2];
            #pragma unroll
            for (int a = 0; a < 2; ++a) {
                wmma::load_matrix_sync(ahi[a], aHI + (mi0 + a) * 16 * AH_STR + k * 16, AH_STR);
                wmma::load_matrix_sync(alo[a], aLO + (mi0 + a) * 16 * AH_STR + k * 16, AH_STR);
            }
            #pragma unroll
            for (int d = 0; d < 2; ++d) {
                wmma::load_matrix_sync(bhi[d], gbh + k * 16 * BW_STR + (ni0 + d) * 16, BW_STR);
                wmma::load_matrix_sync(blo[d], gbl + k * 16 * BW_STR + (ni0 + d) * 16, BW_STR);
            }
            #pragma unroll
            for (int a = 0; a < 2; ++a)
                #pragma unroll
                for (int d = 0; d < 2; ++d) {
                    wmma::mma_sync(c[a][d], ahi[a], bhi[d], c[a][d]);
                    wmma::mma_sync(c[a][d], ahi[a], blo[d], c[a][d]);
                    wmma::mma_sync(c[a][d], alo[a], bhi[d], c[a][d]);
                }
        }
        // order: all A-fragment reads (t==2) / prior-chunk spill stores done before stores
        __syncthreads();

        float* dst = (t == 0) ? (smem + Q_OFF) : (t == 1) ? (smem + K_OFF) : smem;
        #pragma unroll
        for (int a = 0; a < 2; ++a)
            #pragma unroll
            for (int d = 0; d < 2; ++d)
                wmma::store_matrix_sync(dst + (mi0 + a) * 16 * 136 + (ni0 + d) * 16,
                                        c[a][d], 136, wmma::mem_row_major);
    }
    __syncthreads();

    // bias: Q (+scale), K, V
    for (int u = tid; u < NTOK * 128; u += 256) {
        int r = u >> 7, cc = u & 127;
        float* qp = smem + Q_OFF + r * Q_STR + cc;
        *qp = (*qp + b_qkv[cc]) * SCALE;
        smem[K_OFF + r * K_STR + cc] += b_qkv[128 + cc];
        smem[r * V_STR + cc]         += b_qkv[256 + cc];
    }
    __syncthreads();

    // ---------------- Phase 3: attention (fp32 regs; bias+mask AFTER softmax) ---------
    {
        const int head = tid >> 6, lt = tid & 63;
        const bool act = (lt < NTOK);
        const int i = act ? lt : NTOK - 1;

        float4 q4[8];
        const float4* qr = reinterpret_cast<const float4*>(smem + Q_OFF + i * Q_STR + head * DH);
        #pragma unroll
        for (int m = 0; m < 8; ++m) q4[m] = qr[m];

        float s[NTOK];
        const float* kb = smem + K_OFF + head * DH;
        #pragma unroll
        for (int j = 0; j < NTOK; ++j) {
            const float4* kr = reinterpret_cast<const float4*>(kb + j * K_STR);
            float a = 0.f;
            #pragma unroll
            for (int m = 0; m < 8; ++m) {
                float4 k4 = kr[m];
                a += q4[m].x * k4.x + q4[m].y * k4.y + q4[m].z * k4.z + q4[m].w * k4.w;
            }
            s[j] = a;
        }
        float mx = s[0];
        #pragma unroll
        for (int j = 1; j < NTOK; ++j) mx = fmaxf(mx, s[j]);
        float sum = 0.f;
        #pragma unroll
        for (int j = 0; j < NTOK; ++j) { s[j] = __expf(s[j] - mx); sum += s[j]; }
        const float inv = 1.f / sum;
        const int yi = i / 7, xi = i - 7 * (i / 7), li = lab[i];
        #pragma unroll
        for (int j = 0; j < NTOK; ++j) {
            int yj = j / 7, xj = j - 7 * yj;
            float bias = __ldg(rel_table + ((yi - yj + 6) * 13 + (xi - xj + 6)) * NH + head);
            s[j] = s[j] * inv + bias + ((lab[j] != li) ? -100.f : 0.f);
        }
        float oa[32];
        #pragma unroll
        for (int d = 0; d < 32; ++d) oa[d] = 0.f;
        const float* vb = smem + head * DH;     // V lives in AV region
        #pragma unroll
        for (int j = 0; j < NTOK; ++j) {
            float a = s[j];
            const float4* vr = reinterpret_cast<const float4*>(vb + j * V_STR);
            #pragma unroll
            for (int m = 0; m < 8; ++m) {
                float4 v4 = vr[m];
                oa[4*m] += a*v4.x; oa[4*m+1] += a*v4.y; oa[4*m+2] += a*v4.z; oa[4*m+3] += a*v4.w;
            }
        }
        __syncthreads();   // all V reads done -> safe to overwrite AV region with O halves
        if (act) {
            #pragma unroll
            for (int m = 0; m < 8; ++m) {
                float vx = oa[4*m], vy = oa[4*m+1], vz = oa[4*m+2], vw = oa[4*m+3];
                __half h0 = __float2half_rn(vx), h1 = __float2half_rn(vy);
                __half h2 = __float2half_rn(vz), h3 = __float2half_rn(vw);
                __half2* ph = reinterpret_cast<__half2*>(aHI + i * AH_STR + head * DH + 4 * m);
                ph[0] = __halves2half2(h0, h1); ph[1] = __halves2half2(h2, h3);
                __half2* pl = reinterpret_cast<__half2*>(aLO + i * AH_STR + head * DH + 4 * m);
                pl[0] = __floats2half2_rn(vx - __half2float(h0), vy - __half2float(h1));
                pl[1] = __floats2half2_rn(vz - __half2float(h2), vw - __half2float(h3));
            }
        }
        // re-zero pad rows of A (V stores dirtied rows 49..63)
        for (int t2 = tid; t2 < 15 * AH_STR; t2 += 256) {
            int r = 49 + t2 / AH_STR, c2 = t2 % AH_STR;
            aHI[r * AH_STR + c2] = __ushort_as_half(0);
            aLO[r * AH_STR + c2] = __ushort_as_half(0);
        }
    }
    __syncthreads();

    // ---------------- Phase 4: proj GEMM (tile 3, B from global) -> Q buffer -> scatter
    {
        const __half* gbh = g_bhi[3];
        const __half* gbl = g_blo[3];
        FragC c[2][2];
        #pragma unroll
        for (int a = 0; a < 2; ++a)
            #pragma unroll
            for (int d = 0; d < 2; ++d) wmma::fill_fragment(c[a][d], 0.f);
        #pragma unroll 1
        for (int k = 0; k < 8; ++k) {
            FragA ahi[2], alo[2];
            FragB bhi[2], blo[2];
            #pragma unroll
            for (int a = 0; a < 2; ++a) {
                wmma::load_matrix_sync(ahi[a], aHI + (mi0 + a) * 16 * AH_STR + k * 16, AH_STR);
                wmma::load_matrix_sync(alo[a], aLO + (mi0 + a) * 16 * AH_STR + k * 16, AH_STR);
            }
            #pragma unroll
            for (int d = 0; d < 2; ++d) {
                wmma::load_matrix_sync(bhi[d], gbh + k * 16 * BW_STR + (ni0 + d) * 16, BW_STR);
                wmma::load_matrix_sync(blo[d], gbl + k * 16 * BW_STR + (ni0 + d) * 16, BW_STR);
            }
            #pragma unroll
            for (int a = 0; a < 2; ++a)
                #pragma unroll
                for (int d = 0; d < 2; ++d) {
                    wmma::mma_sync(c[a][d], ahi[a], bhi[d], c[a][d]);
                    wmma::mma_sync(c[a][d], ahi[a], blo[d], c[a][d]);
                    wmma::mma_sync(c[a][d], alo[a], bhi[d], c[a][d]);
                }
        }
        __syncthreads();
        #pragma unroll
        for (int a = 0; a < 2; ++a)
            #pragma unroll
            for (int d = 0; d < 2; ++d)
                wmma::store_matrix_sync(smem + Q_OFF + (mi0 + a) * 16 * Q_STR + (ni0 + d) * 16,
                                        c[a][d], Q_STR, wmma::mem_row_major);
    }
    __syncthreads();

    // scatter: window-reverse + roll + bias
    for (int t = tid; t < NTOK * 32; t += 256) {
        int n = t >> 5, c4 = t & 31, i = n / 7, j = n - i * 7;
        int rg = wy * 7 + i + SHIFT; if (rg >= HWDIM) rg -= HWDIM;
        int cg = wx * 7 + j + SHIFT; if (cg >= HWDIM) cg -= HWDIM;
        float4 v  = reinterpret_cast<const float4*>(smem + Q_OFF + n * Q_STR)[c4];
        float4 bb = reinterpret_cast<const float4*>(b_proj)[c4];
        v.x += bb.x; v.y += bb.y; v.z += bb.z; v.w += bb.w;
        reinterpret_cast<float4*>(
            out + ((size_t)(b * HWDIM + rg) * HWDIM + cg) * CCH)[c4] = v;
    }
}

extern "C" void kernel_launch(void* const* d_in, const int* in_sizes, int n_in,
                              void* d_out, int out_size)
{
    const float* x         = (const float*)d_in[0];
    const float* w_qkv     = (const float*)d_in[1];
    const float* b_qkv     = (const float*)d_in[2];
    const float* w_proj    = (const float*)d_in[3];
    const float* b_proj    = (const float*)d_in[4];
    const float* rel_table = (const float*)d_in[5];
    float* out = (float*)d_out;

    cudaFuncSetAttribute(swin_block_kernel,
                         cudaFuncAttributeMaxDynamicSharedMemorySize, SMEM_BYTES);
    prep_kernel<<<(4 * 128 * 136 + 255) / 256, 256>>>(w_qkv, w_proj);
    swin_block_kernel<<<4096, 256, SMEM_BYTES>>>(x, b_qkv, b_proj, rel_table, out);
}

// round 14
// speedup vs baseline: 3.1901x; 1.0005x over previous
#include <cuda_runtime.h>
#include <cuda_fp16.h>
#include <mma.h>
#include <cstdint>

using namespace nvcuda;

#define NTOK   49
#define CCH    128
#define NH     4
#define DH     32
#define HWDIM  56
#define SHIFT  3
#define SCALE  0.17677669529663687f

// smem layout (float offsets), all WMMA bases/strides 32B-aligned
// AV region [0,8704): aHI halves (0..4352 fl), aLO halves (4352..8704 fl); later V fp32 [64][136]
#define A_LO_OFF  4352
#define AH_STR    136          // halves
#define V_STR     136          // floats
#define Q_OFF     8704         // [49][136] fp32 (spill rows 49-63 -> K region, overwritten)
#define Q_STR     136
#define K_OFF     15368        // [64][136] fp32 (incl spill rows)
#define K_STR     136
#define SMEM_FLOATS 24072
#define SMEM_BYTES  (SMEM_FLOATS * 4)   // 96288 B -> 2 CTAs/SM
#define BW_STR 136             // global prepped weight stride (halves)

typedef wmma::fragment<wmma::matrix_a, 16, 16, 16, __half, wmma::row_major> FragA;
typedef wmma::fragment<wmma::matrix_b, 16, 16, 16, __half, wmma::row_major> FragB;
typedef wmma::fragment<wmma::accumulator, 16, 16, 16, float> FragC;

// prepped weights: [4 tiles][128k x 136n] halves (tiles 0..2 = qkv cols t*128.., 3 = proj)
__device__ __align__(16) __half g_bhi[4][128 * 136];
__device__ __align__(16) __half g_blo[4][128 * 136];

__global__ void prep_kernel(const float* __restrict__ w_qkv, const float* __restrict__ w_proj)
{
    int idx = blockIdx.x * 256 + threadIdx.x;
    if (idx >= 4 * 128 * 136) return;
    int t = idx / (128 * 136), rem = idx % (128 * 136);
    int k = rem / 136, n = rem % 136;
    float v = 0.f;
    if (n < 128) v = (t < 3) ? w_qkv[k * 384 + t * 128 + n] : w_proj[k * 128 + n];
    __half h = __float2half_rn(v);
    g_bhi[t][k * 136 + n] = h;
    g_blo[t][k * 136 + n] = __float2half_rn(v - __half2float(h));
}

__global__ __launch_bounds__(256, 2)
void swin_block_kernel(const float* __restrict__ x,
                       const float* __restrict__ b_qkv,
                       const float* __restrict__ b_proj,
                       const float* __restrict__ rel_table,
                       float* __restrict__ out)
{
    extern __shared__ float smem[];
    __shared__ int lab[NTOK];

    __half* aHI = reinterpret_cast<__half*>(smem);
    __half* aLO = reinterpret_cast<__half*>(smem + A_LO_OFF);

    const int tid = threadIdx.x, warp = tid >> 5;
    const int b = blockIdx.x >> 6, widx = blockIdx.x & 63;
    const int wy = widx >> 3, wx = widx & 7;
    const int mi0 = (warp >> 2) * 2;     // {0,2}
    const int ni0 = (warp & 3) * 2;      // {0,2,4,6}

    // ---------------- Phase 1: rolled window -> hi/lo halves; labels; zero pad rows ----
    for (int t = tid; t < NTOK * 32; t += 256) {
        int n = t >> 5, c4 = t & 31, i = n / 7, j = n - i * 7;
        int r  = wy * 7 + i + SHIFT; if (r  >= HWDIM) r  -= HWDIM;
        int cc = wx * 7 + j + SHIFT; if (cc >= HWDIM) cc -= HWDIM;
        float4 v = reinterpret_cast<const float4*>(
            x + ((size_t)(b * HWDIM + r) * HWDIM + cc) * CCH)[c4];
        __half h0 = __float2half_rn(v.x), h1 = __float2half_rn(v.y);
        __half h2 = __float2half_rn(v.z), h3 = __float2half_rn(v.w);
        __half2* ph = reinterpret_cast<__half2*>(aHI + n * AH_STR + c4 * 4);
        ph[0] = __halves2half2(h0, h1); ph[1] = __halves2half2(h2, h3);
        __half2* pl = reinterpret_cast<__half2*>(aLO + n * AH_STR + c4 * 4);
        pl[0] = __floats2half2_rn(v.x - __half2float(h0), v.y - __half2float(h1));
        pl[1] = __floats2half2_rn(v.z - __half2float(h2), v.w - __half2float(h3));
    }
    for (int t = tid; t < 15 * AH_STR; t += 256) {   // zero rows 49..63
        int r = 49 + t / AH_STR, c = t % AH_STR;
        aHI[r * AH_STR + c] = __ushort_as_half(0);
        aLO[r * AH_STR + c] = __ushort_as_half(0);
    }
    if (tid < NTOK) {
        int i = tid / 7, j = tid - (tid / 7) * 7;
        int sh = wy * 7 + i, sw = wx * 7 + j;
        lab[tid] = ((sh < 49) ? 0 : (sh < 53) ? 1 : 2) * 3 + ((sw < 49) ? 0 : (sw < 53) ? 1 : 2);
    }
    __syncthreads();

    // ---------------- Phase 2: QKV GEMM via WMMA; B fragments direct from global -----
    #pragma unroll 1
    for (int t = 0; t < 3; ++t) {
        const __half* gbh = g_bhi[t];
        const __half* gbl = g_blo[t];

        FragC c[2][2];
        #pragma unroll
        for (int a = 0; a < 2; ++a)
            #pragma unroll
            for (int d = 0; d < 2; ++d) wmma::fill_fragment(c[a][d], 0.f);

        #pragma unroll 1
        for (int k = 0; k < 8; ++k) {
            FragA ahi[2], alo[2];
            FragB bhi[2], blo[2];
            #pragma unroll
            for (int a = 0; a < 2; ++a) {
                wmma::load_matrix_sync(ahi[a], aHI + (mi0 + a) * 16 * AH_STR + k * 16, AH_STR);
                wmma::load_matrix_sync(alo[a], aLO + (mi0 + a) * 16 * AH_STR + k * 16, AH_STR);
            }
            #pragma unroll
            for (int d = 0; d < 2; ++d) {
                wmma::load_matrix_sync(bhi[d], gbh + k * 16 * BW_STR + (ni0 + d) * 16, BW_STR);
                wmma::load_matrix_sync(blo[d], gbl + k * 16 * BW_STR + (ni0 + d) * 16, BW_STR);
            }
            #pragma unroll
            for (int a = 0; a < 2; ++a)
                #pragma unroll
                for (int d = 0; d < 2; ++d) {
                    wmma::mma_sync(c[a][d], ahi[a], bhi[d], c[a][d]);
                    wmma::mma_sync(c[a][d], ahi[a], blo[d], c[a][d]);
                    wmma::mma_sync(c[a][d], alo[a], bhi[d], c[a][d]);
                }
        }
        // order: all A-fragment reads (t==2) / prior-chunk spill stores done before stores
        __syncthreads();

        float* dst = (t == 0) ? (smem + Q_OFF) : (t == 1) ? (smem + K_OFF) : smem;
        #pragma unroll
        for (int a = 0; a < 2; ++a)
            #pragma unroll
            for (int d = 0; d < 2; ++d)
                wmma::store_matrix_sync(dst + (mi0 + a) * 16 * 136 + (ni0 + d) * 16,
                                        c[a][d], 136, wmma::mem_row_major);
    }
    __syncthreads();

    // bias: Q (+scale), K, V
    for (int u = tid; u < NTOK * 128; u += 256) {
        int r = u >> 7, cc = u & 127;
        float* qp = smem + Q_OFF + r * Q_STR + cc;
        *qp = (*qp + b_qkv[cc]) * SCALE;
        smem[K_OFF + r * K_STR + cc] += b_qkv[128 + cc];
        smem[r * V_STR + cc]         += b_qkv[256 + cc];
    }
    __syncthreads();

    // ---------------- Phase 3: attention (fp32 regs; bias+mask AFTER softmax) ---------
    {
        const int head = tid >> 6, lt = tid & 63;
        const bool act = (lt < NTOK);
        const int i = act ? lt : NTOK - 1;

        float4 q4[8];
        const float4* qr = reinterpret_cast<const float4*>(smem + Q_OFF + i * Q_STR + head * DH);
        #pragma unroll
        for (int m = 0; m < 8; ++m) q4[m] = qr[m];

        float s[NTOK];
        const float* kb = smem + K_OFF + head * DH;
        #pragma unroll
        for (int j = 0; j < NTOK; ++j) {
            const float4* kr = reinterpret_cast<const float4*>(kb + j * K_STR);
            float a = 0.f;
            #pragma unroll
            for (int m = 0; m < 8; ++m) {
                float4 k4 = kr[m];
                a += q4[m].x * k4.x + q4[m].y * k4.y + q4[m].z * k4.z + q4[m].w * k4.w;
            }
            s[j] = a;
        }
        float mx = s[0];
        #pragma unroll
        for (int j = 1; j < NTOK; ++j) mx = fmaxf(mx, s[j]);
        float sum = 0.f;
        #pragma unroll
        for (int j = 0; j < NTOK; ++j) { s[j] = __expf(s[j] - mx); sum += s[j]; }
        const float inv = 1.f / sum;
        const int yi = i / 7, xi = i - 7 * (i / 7), li = lab[i];
        #pragma unroll
        for (int j = 0; j < NTOK; ++j) {
            int yj = j / 7, xj = j - 7 * yj;
            float bias = __ldg(rel_table + ((yi - yj + 6) * 13 + (xi - xj + 6)) * NH + head);
            s[j] = s[j] * inv + bias + ((lab[j] != li) ? -100.f : 0.f);
        }
        float oa[32];
        #pragma unroll
        for (int d = 0; d < 32; ++d) oa[d] = 0.f;
        const float* vb = smem + head * DH;     // V lives in AV region
        #pragma unroll
        for (int j = 0; j < NTOK; ++j) {
            float a = s[j];
            const float4* vr = reinterpret_cast<const float4*>(vb + j * V_STR);
            #pragma unroll
            for (int m = 0; m < 8; ++m) {
                float4 v4 = vr[m];
                oa[4*m] += a*v4.x; oa[4*m+1] += a*v4.y; oa[4*m+2] += a*v4.z; oa[4*m+3] += a*v4.w;
            }
        }
        __syncthreads();   // all V reads done -> safe to overwrite AV region with O halves
        if (act) {
            #pragma unroll
            for (int m = 0; m < 8; ++m) {
                float vx = oa[4*m], vy = oa[4*m+1], vz = oa[4*m+2], vw = oa[4*m+3];
                __half h0 = __float2half_rn(vx), h1 = __float2half_rn(vy);
                __half h2 = __float2half_rn(vz), h3 = __float2half_rn(vw);
                __half2* ph = reinterpret_cast<__half2*>(aHI + i * AH_STR + head * DH + 4 * m);
                ph[0] = __halves2half2(h0, h1); ph[1] = __halves2half2(h2, h3);
                __half2* pl = reinterpret_cast<__half2*>(aLO + i * AH_STR + head * DH + 4 * m);
                pl[0] = __floats2half2_rn(vx - __half2float(h0), vy - __half2float(h1));
                pl[1] = __floats2half2_rn(vz - __half2float(h2), vw - __half2float(h3));
            }
        }
        // re-zero pad rows of A (V stores dirtied rows 49..63)
        for (int t2 = tid; t2 < 15 * AH_STR; t2 += 256) {
            int r = 49 + t2 / AH_STR, c2 = t2 % AH_STR;
            aHI[r * AH_STR + c2] = __ushort_as_half(0);
            aLO[r * AH_STR + c2] = __ushort_as_half(0);
        }
    }
    __syncthreads();

    // ---------------- Phase 4: proj GEMM (tile 3, B from global) -> Q buffer -> scatter
    {
        const __half* gbh = g_bhi[3];
        const __half* gbl = g_blo[3];
        FragC c[2][2];
        #pragma unroll
        for (int a = 0; a < 2; ++a)
            #pragma unroll
            for (int d = 0; d < 2; ++d) wmma::fill_fragment(c[a][d], 0.f);
        #pragma unroll 1
        for (int k = 0; k < 8; ++k) {
            FragA ahi[2], alo[2];
            FragB bhi[2], blo[2];
            #pragma unroll
            for (int a = 0; a < 2; ++a) {
                wmma::load_matrix_sync(ahi[a], aHI + (mi0 + a) * 16 * AH_STR + k * 16, AH_STR);
                wmma::load_matrix_sync(alo[a], aLO + (mi0 + a) * 16 * AH_STR + k * 16, AH_STR);
            }
            #pragma unroll
            for (int d = 0; d < 2; ++d) {
                wmma::load_matrix_sync(bhi[d], gbh + k * 16 * BW_STR + (ni0 + d) * 16, BW_STR);
                wmma::load_matrix_sync(blo[d], gbl + k * 16 * BW_STR + (ni0 + d) * 16, BW_STR);
            }
            #pragma unroll
            for (int a = 0; a < 2; ++a)
                #pragma unroll
                for (int d = 0; d < 2; ++d) {
                    wmma::mma_sync(c[a][d], ahi[a], bhi[d], c[a][d]);
                    wmma::mma_sync(c[a][d], ahi[a], blo[d], c[a][d]);
                    wmma::mma_sync(c[a][d], alo[a], bhi[d], c[a][d]);
                }
        }
        __syncthreads();
        #pragma unroll
        for (int a = 0; a < 2; ++a)
            #pragma unroll
            for (int d = 0; d < 2; ++d)
                wmma::store_matrix_sync(smem + Q_OFF + (mi0 + a) * 16 * Q_STR + (ni0 + d) * 16,
                                        c[a][d], Q_STR, wmma::mem_row_major);
    }
    __syncthreads();

    // scatter: window-reverse + roll + bias
    for (int t = tid; t < NTOK * 32; t += 256) {
        int n = t >> 5, c4 = t & 31, i = n / 7, j = n - i * 7;
        int rg = wy * 7 + i + SHIFT; if (rg >= HWDIM) rg -= HWDIM;
        int cg = wx * 7 + j + SHIFT; if (cg >= HWDIM) cg -= HWDIM;
        float4 v  = reinterpret_cast<const float4*>(smem + Q_OFF + n * Q_STR)[c4];
        float4 bb = reinterpret_cast<const float4*>(b_proj)[c4];
        v.x += bb.x; v.y += bb.y; v.z += bb.z; v.w += bb.w;
        reinterpret_cast<float4*>(
            out + ((size_t)(b * HWDIM + rg) * HWDIM + cg) * CCH)[c4] = v;
    }
}

extern "C" void kernel_launch(void* const* d_in, const int* in_sizes, int n_in,
                              void* d_out, int out_size)
{
    const float* x         = (const float*)d_in[0];
    const float* w_qkv     = (const float*)d_in[1];
    const float* b_qkv     = (const float*)d_in[2];
    const float* w_proj    = (const float*)d_in[3];
    const float* b_proj    = (const float*)d_in[4];
    const float* rel_table = (const float*)d_in[5];
    float* out = (float*)d_out;

    cudaFuncSetAttribute(swin_block_kernel,
                         cudaFuncAttributeMaxDynamicSharedMemorySize, SMEM_BYTES);
    prep_kernel<<<(4 * 128 * 136 + 255) / 256, 256>>>(w_qkv, w_proj);
    swin_block_kernel<<<4096, 256, SMEM_BYTES>>>(x, b_qkv, b_proj, rel_table, out);
}

// round 15
// speedup vs baseline: 3.3271x; 1.0429x over previous
#include <cuda_runtime.h>
#include <cuda_fp16.h>
#include <mma.h>
#include <cstdint>

using namespace nvcuda;

#define NTOK   49
#define CCH    128
#define NH     4
#define DH     32
#define HWDIM  56
#define SHIFT  3
#define SCALE  0.17677669529663687f

// smem layout (float offsets), all WMMA bases/strides 32B-aligned
// AV region [0,8704): aHI halves (0..4352 fl), aLO halves (4352..8704 fl); later V fp32 [64][136]
#define A_LO_OFF  4352
#define AH_STR    136          // halves
#define V_STR     136          // floats
#define Q_OFF     8704         // [49][136] fp32 (spill rows 49-63 -> K region, overwritten)
#define Q_STR     136
#define K_OFF     15368        // [64][136] fp32 (incl spill rows)
#define K_STR     136
#define SMEM_FLOATS 24072
#define SMEM_BYTES  (SMEM_FLOATS * 4)   // 96288 B -> 2 CTAs/SM

typedef wmma::fragment<wmma::matrix_a, 16, 16, 16, __half, wmma::row_major> FragA;
typedef wmma::fragment<wmma::matrix_b, 16, 16, 16, __half, wmma::row_major> FragB;
typedef wmma::fragment<wmma::accumulator, 16, 16, 16, float> FragC;

// prepped weights, FRAGMENT-PACKED: [4 tiles][8 kf][8 nf][16x16] halves, each
// fragment contiguous (512B, ld=16) so a warp fragment load hits 4 cache lines.
__device__ __align__(16) __half g_bhi[4][16384];
__device__ __align__(16) __half g_blo[4][16384];

__global__ void prep_kernel(const float* __restrict__ w_qkv, const float* __restrict__ w_proj)
{
    int idx = blockIdx.x * 256 + threadIdx.x;
    if (idx >= 4 * 128 * 128) return;
    int t = idx >> 14, rem = idx & 16383;
    int k = rem >> 7, n = rem & 127;
    float v = (t < 3) ? w_qkv[k * 384 + t * 128 + n] : w_proj[k * 128 + n];
    __half h = __float2half_rn(v);
    int off = (((k >> 4) * 8 + (n >> 4)) << 8) + ((k & 15) << 4) + (n & 15);
    g_bhi[t][off] = h;
    g_blo[t][off] = __float2half_rn(v - __half2float(h));
}

__global__ __launch_bounds__(256, 2)
void swin_block_kernel(const float* __restrict__ x,
                       const float* __restrict__ b_qkv,
                       const float* __restrict__ b_proj,
                       const float* __restrict__ rel_table,
                       float* __restrict__ out)
{
    extern __shared__ float smem[];
    __shared__ int lab[NTOK];

    __half* aHI = reinterpret_cast<__half*>(smem);
    __half* aLO = reinterpret_cast<__half*>(smem + A_LO_OFF);

    const int tid = threadIdx.x, warp = tid >> 5;
    const int b = blockIdx.x >> 6, widx = blockIdx.x & 63;
    const int wy = widx >> 3, wx = widx & 7;
    const int mi0 = (warp >> 2) * 2;     // {0,2}
    const int ni0 = (warp & 3) * 2;      // {0,2,4,6}

    // ---------------- Phase 1: rolled window -> hi/lo halves; labels; zero pad rows ----
    for (int t = tid; t < NTOK * 32; t += 256) {
        int n = t >> 5, c4 = t & 31, i = n / 7, j = n - i * 7;
        int r  = wy * 7 + i + SHIFT; if (r  >= HWDIM) r  -= HWDIM;
        int cc = wx * 7 + j + SHIFT; if (cc >= HWDIM) cc -= HWDIM;
        float4 v = reinterpret_cast<const float4*>(
            x + ((size_t)(b * HWDIM + r) * HWDIM + cc) * CCH)[c4];
        __half h0 = __float2half_rn(v.x), h1 = __float2half_rn(v.y);
        __half h2 = __float2half_rn(v.z), h3 = __float2half_rn(v.w);
        __half2* ph = reinterpret_cast<__half2*>(aHI + n * AH_STR + c4 * 4);
        ph[0] = __halves2half2(h0, h1); ph[1] = __halves2half2(h2, h3);
        __half2* pl = reinterpret_cast<__half2*>(aLO + n * AH_STR + c4 * 4);
        pl[0] = __floats2half2_rn(v.x - __half2float(h0), v.y - __half2float(h1));
        pl[1] = __floats2half2_rn(v.z - __half2float(h2), v.w - __half2float(h3));
    }
    for (int t = tid; t < 15 * AH_STR; t += 256) {   // zero rows 49..63
        int r = 49 + t / AH_STR, c = t % AH_STR;
        aHI[r * AH_STR + c] = __ushort_as_half(0);
        aLO[r * AH_STR + c] = __ushort_as_half(0);
    }
    if (tid < NTOK) {
        int i = tid / 7, j = tid - (tid / 7) * 7;
        int sh = wy * 7 + i, sw = wx * 7 + j;
        lab[tid] = ((sh < 49) ? 0 : (sh < 53) ? 1 : 2) * 3 + ((sw < 49) ? 0 : (sw < 53) ? 1 : 2);
    }
    __syncthreads();

    // ---------------- Phase 2: QKV GEMM via WMMA; packed B fragments from global -----
    #pragma unroll 1
    for (int t = 0; t < 3; ++t) {
        const __half* gbh = g_bhi[t];
        const __half* gbl = g_blo[t];

        FragC c[2][2];
        #pragma unroll
        for (int a = 0; a < 2; ++a)
            #pragma unroll
            for (int d = 0; d < 2; ++d) wmma::fill_fragment(c[a][d], 0.f);

        #pragma unroll 1
        for (int k = 0; k < 8; ++k) {
            FragA ahi[2], alo[2];
            FragB bhi[2], blo[2];
            #pragma unroll
            for (int a = 0; a < 2; ++a) {
                wmma::load_matrix_sync(ahi[a], aHI + (mi0 + a) * 16 * AH_STR + k * 16, AH_STR);
                wmma::load_matrix_sync(alo[a], aLO + (mi0 + a) * 16 * AH_STR + k * 16, AH_STR);
            }
            #pragma unroll
            for (int d = 0; d < 2; ++d) {
                const int foff = ((k * 8 + ni0 + d) << 8);
                wmma::load_matrix_sync(bhi[d], gbh + foff, 16);
                wmma::load_matrix_sync(blo[d], gbl + foff, 16);
            }
            #pragma unroll
            for (int a = 0; a < 2; ++a)
                #pragma unroll
                for (int d = 0; d < 2; ++d) {
                    wmma::mma_sync(c[a][d], ahi[a], bhi[d], c[a][d]);
                    wmma::mma_sync(c[a][d], ahi[a], blo[d], c[a][d]);
                    wmma::mma_sync(c[a][d], alo[a], bhi[d], c[a][d]);
                }
        }
        // order: all A-fragment reads (t==2) / prior-chunk spill stores done before stores
        __syncthreads();

        float* dst = (t == 0) ? (smem + Q_OFF) : (t == 1) ? (smem + K_OFF) : smem;
        #pragma unroll
        for (int a = 0; a < 2; ++a)
            #pragma unroll
            for (int d = 0; d < 2; ++d)
                wmma::store_matrix_sync(dst + (mi0 + a) * 16 * 136 + (ni0 + d) * 16,
                                        c[a][d], 136, wmma::mem_row_major);
    }
    __syncthreads();

    // bias: Q (+scale), K, V
    for (int u = tid; u < NTOK * 128; u += 256) {
        int r = u >> 7, cc = u & 127;
        float* qp = smem + Q_OFF + r * Q_STR + cc;
        *qp = (*qp + b_qkv[cc]) * SCALE;
        smem[K_OFF + r * K_STR + cc] += b_qkv[128 + cc];
        smem[r * V_STR + cc]         += b_qkv[256 + cc];
    }
    __syncthreads();

    // ---------------- Phase 3: attention (fp32 regs; bias+mask AFTER softmax) ---------
    {
        const int head = tid >> 6, lt = tid & 63;
        const bool act = (lt < NTOK);
        const int i = act ? lt : NTOK - 1;

        float4 q4[8];
        const float4* qr = reinterpret_cast<const float4*>(smem + Q_OFF + i * Q_STR + head * DH);
        #pragma unroll
        for (int m = 0; m < 8; ++m) q4[m] = qr[m];

        float s[NTOK];
        const float* kb = smem + K_OFF + head * DH;
        #pragma unroll
        for (int j = 0; j < NTOK; ++j) {
            const float4* kr = reinterpret_cast<const float4*>(kb + j * K_STR);
            float a = 0.f;
            #pragma unroll
            for (int m = 0; m < 8; ++m) {
                float4 k4 = kr[m];
                a += q4[m].x * k4.x + q4[m].y * k4.y + q4[m].z * k4.z + q4[m].w * k4.w;
            }
            s[j] = a;
        }
        float mx = s[0];
        #pragma unroll
        for (int j = 1; j < NTOK; ++j) mx = fmaxf(mx, s[j]);
        float sum = 0.f;
        #pragma unroll
        for (int j = 0; j < NTOK; ++j) { s[j] = __expf(s[j] - mx); sum += s[j]; }
        const float inv = 1.f / sum;
        const int yi = i / 7, xi = i - 7 * (i / 7), li = lab[i];
        #pragma unroll
        for (int j = 0; j < NTOK; ++j) {
            int yj = j / 7, xj = j - 7 * yj;
            float bias = __ldg(rel_table + ((yi - yj + 6) * 13 + (xi - xj + 6)) * NH + head);
            s[j] = s[j] * inv + bias + ((lab[j] != li) ? -100.f : 0.f);
        }
        float oa[32];
        #pragma unroll
        for (int d = 0; d < 32; ++d) oa[d] = 0.f;
        const float* vb = smem + head * DH;     // V lives in AV region
        #pragma unroll
        for (int j = 0; j < NTOK; ++j) {
            float a = s[j];
            const float4* vr = reinterpret_cast<const float4*>(vb + j * V_STR);
            #pragma unroll
            for (int m = 0; m < 8; ++m) {
                float4 v4 = vr[m];
                oa[4*m] += a*v4.x; oa[4*m+1] += a*v4.y; oa[4*m+2] += a*v4.z; oa[4*m+3] += a*v4.w;
            }
        }
        __syncthreads();   // all V reads done -> safe to overwrite AV region with O halves
        if (act) {
            #pragma unroll
            for (int m = 0; m < 8; ++m) {
                float vx = oa[4*m], vy = oa[4*m+1], vz = oa[4*m+2], vw = oa[4*m+3];
                __half h0 = __float2half_rn(vx), h1 = __float2half_rn(vy);
                __half h2 = __float2half_rn(vz), h3 = __float2half_rn(vw);
                __half2* ph = reinterpret_cast<__half2*>(aHI + i * AH_STR + head * DH + 4 * m);
                ph[0] = __halves2half2(h0, h1); ph[1] = __halves2half2(h2, h3);
                __half2* pl = reinterpret_cast<__half2*>(aLO + i * AH_STR + head * DH + 4 * m);
                pl[0] = __floats2half2_rn(vx - __half2float(h0), vy - __half2float(h1));
                pl[1] = __floats2half2_rn(vz - __half2float(h2), vw - __half2float(h3));
            }
        }
        // re-zero pad rows of A (V stores dirtied rows 49..63)
        for (int t2 = tid; t2 < 15 * AH_STR; t2 += 256) {
            int r = 49 + t2 / AH_STR, c2 = t2 % AH_STR;
            aHI[r * AH_STR + c2] = __ushort_as_half(0);
            aLO[r * AH_STR + c2] = __ushort_as_half(0);
        }
    }
    __syncthreads();

    // ---------------- Phase 4: proj GEMM (tile 3, packed B) -> Q buffer -> scatter ----
    {
        const __half* gbh = g_bhi[3];
        const __half* gbl = g_blo[3];
        FragC c[2][2];
        #pragma unroll
        for (int a = 0; a < 2; ++a)
            #pragma unroll
            for (int d = 0; d < 2; ++d) wmma::fill_fragment(c[a][d], 0.f);
        #pragma unroll 1
        for (int k = 0; k < 8; ++k) {
            FragA ahi[2], alo[2];
            FragB bhi[2], blo[2];
            #pragma unroll
            for (int a = 0; a < 2; ++a) {
                wmma::load_matrix_sync(ahi[a], aHI + (mi0 + a) * 16 * AH_STR + k * 16, AH_STR);
                wmma::load_matrix_sync(alo[a], aLO + (mi0 + a) * 16 * AH_STR + k * 16, AH_STR);
            }
            #pragma unroll
            for (int d = 0; d < 2; ++d) {
                const int foff = ((k * 8 + ni0 + d) << 8);
                wmma::load_matrix_sync(bhi[d], gbh + foff, 16);
                wmma::load_matrix_sync(blo[d], gbl + foff, 16);
            }
            #pragma unroll
            for (int a = 0; a < 2; ++a)
                #pragma unroll
                for (int d = 0; d < 2; ++d) {
                    wmma::mma_sync(c[a][d], ahi[a], bhi[d], c[a][d]);
                    wmma::mma_sync(c[a][d], ahi[a], blo[d], c[a][d]);
                    wmma::mma_sync(c[a][d], alo[a], bhi[d], c[a][d]);
                }
        }
        __syncthreads();
        #pragma unroll
        for (int a = 0; a < 2; ++a)
            #pragma unroll
            for (int d = 0; d < 2; ++d)
                wmma::store_matrix_sync(smem + Q_OFF + (mi0 + a) * 16 * Q_STR + (ni0 + d) * 16,
                                        c[a][d], Q_STR, wmma::mem_row_major);
    }
    __syncthreads();

    // scatter: window-reverse + roll + bias
    for (int t = tid; t < NTOK * 32; t += 256) {
        int n = t >> 5, c4 = t & 31, i = n / 7, j = n - i * 7;
        int rg = wy * 7 + i + SHIFT; if (rg >= HWDIM) rg -= HWDIM;
        int cg = wx * 7 + j + SHIFT; if (cg >= HWDIM) cg -= HWDIM;
        float4 v  = reinterpret_cast<const float4*>(smem + Q_OFF + n * Q_STR)[c4];
        float4 bb = reinterpret_cast<const float4*>(b_proj)[c4];
        v.x += bb.x; v.y += bb.y; v.z += bb.z; v.w += bb.w;
        reinterpret_cast<float4*>(
            out + ((size_t)(b * HWDIM + rg) * HWDIM + cg) * CCH)[c4] = v;
    }
}

extern "C" void kernel_launch(void* const* d_in, const int* in_sizes, int n_in,
                              void* d_out, int out_size)
{
    const float* x         = (const float*)d_in[0];
    const float* w_qkv     = (const float*)d_in[1];
    const float* b_qkv     = (const float*)d_in[2];
    const float* w_proj    = (const float*)d_in[3];
    const float* b_proj    = (const float*)d_in[4];
    const float* rel_table = (const float*)d_in[5];
    float* out = (float*)d_out;

    cudaFuncSetAttribute(swin_block_kernel,
                         cudaFuncAttributeMaxDynamicSharedMemorySize, SMEM_BYTES);
    prep_kernel<<<(4 * 128 * 128 + 255) / 256, 256>>>(w_qkv, w_proj);
    swin_block_kernel<<<4096, 256, SMEM_BYTES>>>(x, b_qkv, b_proj, rel_table, out);
}